// round 12
// baseline (speedup 1.0000x reference)
#include <cuda_runtime.h>
#include <cuda_bf16.h>
#include <cuda_fp16.h>
#include <math.h>
#include <stdint.h>

// ---------------------------------------------------------------------------
// SpatialModel: 3-layer GATConv on two graphs (N=50000, E=800000), mean pool,
// MLP head -> [1,3] logits.
//
// R12: CSR chain shortened -- loop_attr (mean edge col) computed inline in the
// aggregation loop (deletes lsum atomics/memset/lattr array), 2 edges/thread
// in the E-scan kernels. Otherwise R11: two-stream per-graph pipeline, batched
// CSR on side stream, fp16 h, single-pass softmax, K-chunked mma GEMMs.
// ---------------------------------------------------------------------------

#define MAX_N 50000
#define MAX_E 800000
#define TILE 512

__device__ __align__(16) __half g_hh[2][MAX_N * 128];
__device__ float g_x[2][MAX_N * 128];
__device__ float g_hs[2][MAX_N];
__device__ float g_hd[2][MAX_N];
__device__ int   g_deg[2][MAX_N];
__device__ int   g_offs[2][MAX_N + 1];
__device__ int   g_cursor[2][MAX_N];
__device__ __align__(16) float2 g_csre[2][MAX_E];
__device__ int   g_tsum[2][128];
__device__ float g_c[3];
__device__ unsigned g_maxhs[6];     // [layer*2 + graph]
__device__ float g_gvec[128];
__device__ __align__(16) __nv_bfloat16 g_wbh[2][128 * 128];
__device__ __align__(16) __nv_bfloat16 g_wbl[2][128 * 128];

// ---------------------------------------------------------------------------
__device__ __forceinline__ uint32_t smem_u32(const void* p) {
    uint32_t a;
    asm("{ .reg .u64 t; cvta.to.shared.u64 t, %1; cvt.u32.u64 %0, t; }"
        : "=r"(a) : "l"(p));
    return a;
}
__device__ __forceinline__ unsigned fkey(float f) {
    int i = __float_as_int(f);
    return i >= 0 ? ((unsigned)i | 0x80000000u) : ~(unsigned)i;
}
__device__ __forceinline__ float funkey(unsigned k) {
    return (k & 0x80000000u) ? __int_as_float((int)(k & 0x7FFFFFFFu))
                             : __int_as_float((int)~k);
}
#define LDSM_X4(r0, r1, r2, r3, addr)                                          \
    asm volatile("ldmatrix.sync.aligned.m8n8.x4.shared.b16 {%0,%1,%2,%3}, [%4];" \
                 : "=r"(r0), "=r"(r1), "=r"(r2), "=r"(r3) : "r"(addr))
#define LDSM_X4_T(r0, r1, r2, r3, addr)                                        \
    asm volatile("ldmatrix.sync.aligned.m8n8.x4.trans.shared.b16 {%0,%1,%2,%3}, [%4];" \
                 : "=r"(r0), "=r"(r1), "=r"(r2), "=r"(r3) : "r"(addr))
__device__ __forceinline__ void mma16816(float* c, uint32_t a0, uint32_t a1,
                                         uint32_t a2, uint32_t a3,
                                         uint32_t b0, uint32_t b1) {
    asm volatile(
        "mma.sync.aligned.m16n8k16.row.col.f32.bf16.bf16.f32 "
        "{%0,%1,%2,%3}, {%4,%5,%6,%7}, {%8,%9}, {%0,%1,%2,%3};"
        : "+f"(c[0]), "+f"(c[1]), "+f"(c[2]), "+f"(c[3])
        : "r"(a0), "r"(a1), "r"(a2), "r"(a3), "r"(b0), "r"(b1));
}

// ---------------------------------------------------------------------------
// batched in-degree histogram, 2 edges per thread
__global__ void build_deg_k(const int* __restrict__ ei0, const int* __restrict__ ei1,
                            int* deg, int E) {
    int i = (blockIdx.x * blockDim.x + threadIdx.x) * 2;
    if (i >= 2 * E) return;
    int g = (i >= E);
    int j = i - g * E;
    const int* dst = (g ? ei1 : ei0) + E;
    int d0 = dst[j];
    int d1 = dst[j + 1];        // E even: pair never straddles graphs
    atomicAdd(&deg[g * MAX_N + d0], 1);
    atomicAdd(&deg[g * MAX_N + d1], 1);
}

__global__ void scan1_k(const int* __restrict__ deg, int* tsum, int n, int nT) {
    __shared__ int sh[256];
    int bx = blockIdx.x, t = threadIdx.x;
    int g = (bx >= nT);
    int b = bx - g * nT;
    const int* dg = deg + g * MAX_N;
    int i0 = b * TILE;
    int s = 0;
    int i = i0 + t;        if (i < n) s += dg[i];
    i = i0 + 256 + t;      if (i < n) s += dg[i];
    sh[t] = s;
    __syncthreads();
    for (int o = 128; o; o >>= 1) { if (t < o) sh[t] += sh[t + o]; __syncthreads(); }
    if (t == 0) tsum[g * 128 + b] = sh[0];
}
__global__ void scan2_k(int* tsum, int nT) {
    __shared__ int sh[256];
    int t = threadIdx.x;
    int g = t >> 7, tl = t & 127;
    int v0 = (tl < nT) ? tsum[g * 128 + tl] : 0;
    sh[t] = v0;
    __syncthreads();
    for (int d = 1; d < 128; d <<= 1) {
        int v = (tl >= d) ? sh[t - d] : 0;
        __syncthreads();
        sh[t] += v;
        __syncthreads();
    }
    if (tl < nT) tsum[g * 128 + tl] = sh[t] - v0;
}
__global__ void scan3_k(const int* __restrict__ deg, const int* __restrict__ tsum,
                        int* offs, int* cursor, int n, int nT) {
    __shared__ int sh[TILE];
    int bx = blockIdx.x, t = threadIdx.x;
    int g = (bx >= nT);
    int b = bx - g * nT;
    const int* dg = deg + g * MAX_N;
    const int* ts = tsum + g * 128;
    int* of = offs + g * (MAX_N + 1);
    int* cu = cursor + g * MAX_N;
    int i = b * TILE + t;
    int d = (i < n) ? dg[i] : 0;
    sh[t] = d;
    __syncthreads();
    for (int o = 1; o < TILE; o <<= 1) {
        int v = (t >= o) ? sh[t - o] : 0;
        __syncthreads();
        sh[t] += v;
        __syncthreads();
    }
    if (i < n) {
        int base = ts[b];
        int off = base + sh[t] - d;
        of[i] = off;
        cu[i] = off;
        if (i == n - 1) of[n] = base + sh[t];
    }
}

// batched scatter, 2 edges per thread
__global__ void scatter_k(const int* __restrict__ ei0, const float* __restrict__ col0,
                          const int* __restrict__ ei1, const float* __restrict__ col1,
                          int* cursor, float2* csre, int E) {
    int i = (blockIdx.x * blockDim.x + threadIdx.x) * 2;
    if (i >= 2 * E) return;
    int g = (i >= E);
    int j = i - g * E;
    const int* ei = g ? ei1 : ei0;
    const float* col = g ? col1 : col0;
    int* cur = cursor + g * MAX_N;
    float2* cs = csre + (size_t)g * MAX_E;
    int s0 = ei[j], s1 = ei[j + 1];
    int d0 = ei[E + j], d1 = ei[E + j + 1];
    float c0 = col[j], c1 = col[j + 1];
    int p0 = atomicAdd(&cur[d0], 1);
    int p1 = atomicAdd(&cur[d1], 1);
    cs[p0] = make_float2(__int_as_float(s0), c0);
    cs[p1] = make_float2(__int_as_float(s1), c1);
}

// ---------------------------------------------------------------------------
__global__ void wsplit_k(const float* __restrict__ W, __nv_bfloat16* hi,
                         __nv_bfloat16* lo, int n) {
    int i = blockIdx.x * blockDim.x + threadIdx.x;
    if (i >= n) return;
    float v = W[i];
    __nv_bfloat16 h = __float2bfloat16_rn(v);
    hi[i] = h;
    lo[i] = __float2bfloat16_rn(v - __bfloat162float(h));
}

__global__ void cscalar3_k(const float* __restrict__ We1, const float* __restrict__ ae1,
                           const float* __restrict__ We2, const float* __restrict__ ae2,
                           const float* __restrict__ We3, const float* __restrict__ ae3,
                           float* out) {
    int w = threadIdx.x >> 5, lane = threadIdx.x & 31;
    if (w >= 3) return;
    const float* We = (w == 0) ? We1 : (w == 1) ? We2 : We3;
    const float* ae = (w == 0) ? ae1 : (w == 1) ? ae2 : ae3;
    int C = (w == 2) ? 64 : 128;
    float s = 0.f;
    for (int k = lane; k < C; k += 32) s += We[k] * ae[k];
    #pragma unroll
    for (int o = 16; o; o >>= 1) s += __shfl_xor_sync(0xffffffffu, s, o);
    if (lane == 0) out[w] = s;
}

// ---------------------------------------------------------------------------
__global__ void __launch_bounds__(256)
gemm7_k(const float* __restrict__ x, const float* __restrict__ W,
        const float* __restrict__ asrc, const float* __restrict__ adst,
        __half* __restrict__ h, float* __restrict__ hs, float* __restrict__ hd,
        unsigned* __restrict__ gmax, int M) {
    __shared__ float Ws[7 * 128], As[128], Ad[128];
    __shared__ float wmax[8];
    int t = threadIdx.x;
    for (int i = t; i < 7 * 128; i += 256) Ws[i] = W[i];
    if (t < 128) { As[t] = asrc[t]; Ad[t] = adst[t]; }
    __syncthreads();
    int r = blockIdx.x * 8 + (t >> 5);
    bool active = (r < M);
    int lane = t & 31, c0 = lane * 4;
    float s = 0.f, d = 0.f;
    if (active) {
        float xv[7];
        #pragma unroll
        for (int k = 0; k < 7; k++) xv[k] = x[(size_t)r * 7 + k];
        float out[4];
        #pragma unroll
        for (int j = 0; j < 4; j++) {
            float acc = 0.f;
            #pragma unroll
            for (int k = 0; k < 7; k++) acc += xv[k] * Ws[k * 128 + c0 + j];
            out[j] = acc;
        }
        __half2 p0 = __floats2half2_rn(out[0], out[1]);
        __half2 p1 = __floats2half2_rn(out[2], out[3]);
        uint2 u = make_uint2(*(uint32_t*)&p0, *(uint32_t*)&p1);
        *(uint2*)(h + (size_t)r * 128 + c0) = u;
        s = out[0] * As[c0] + out[1] * As[c0 + 1] + out[2] * As[c0 + 2] + out[3] * As[c0 + 3];
        d = out[0] * Ad[c0] + out[1] * Ad[c0 + 1] + out[2] * Ad[c0 + 2] + out[3] * Ad[c0 + 3];
        #pragma unroll
        for (int o = 16; o; o >>= 1) {
            s += __shfl_xor_sync(0xffffffffu, s, o);
            d += __shfl_xor_sync(0xffffffffu, d, o);
        }
        if (lane == 0) { hs[r] = s; hd[r] = d; }
    }
    if (lane == 0) wmax[t >> 5] = active ? s : -3.4e38f;
    __syncthreads();
    if (t == 0) {
        float m = wmax[0];
        #pragma unroll
        for (int i = 1; i < 8; i++) m = fmaxf(m, wmax[i]);
        atomicMax(gmax, fkey(m));
    }
}

// ---------------------------------------------------------------------------
template <int CN>
__global__ void __launch_bounds__(256, 2)
gemm_mma_k(const float* __restrict__ A, const __nv_bfloat16* __restrict__ Bh,
           const __nv_bfloat16* __restrict__ Bl,
           const float* __restrict__ asrc, const float* __restrict__ adst,
           __half* __restrict__ H, float* __restrict__ hs, float* __restrict__ hd,
           unsigned* __restrict__ gmax, int M) {
    extern __shared__ char smem[];
    constexpr int SA = 72;
    constexpr int SB = CN + 8;
    constexpr int AH = 0;
    constexpr int AL = 128 * SA * 2;
    constexpr int BH = 2 * AL;
    constexpr int BL = BH + 64 * SB * 2;
    constexpr int NT = CN / 16;
    constexpr int NC8 = CN / 8;

    int tid = threadIdx.x, lane = tid & 31, warp = tid >> 5;
    const int rowBase = blockIdx.x * 128;

    __nv_bfloat16* as_h = (__nv_bfloat16*)(smem + AH);
    __nv_bfloat16* as_l = (__nv_bfloat16*)(smem + AL);
    __nv_bfloat16* bs_h = (__nv_bfloat16*)(smem + BH);
    __nv_bfloat16* bs_l = (__nv_bfloat16*)(smem + BL);

    int wm = warp >> 1, wn = warp & 1;
    int m0 = wm * 32, n0 = wn * (CN / 2);

    float acc[2][NT][4];
    #pragma unroll
    for (int a = 0; a < 2; a++)
        #pragma unroll
        for (int b = 0; b < NT; b++)
            #pragma unroll
            for (int q = 0; q < 4; q++) acc[a][b][q] = 0.f;

    int lr = lane & 15, lc = lane >> 4;
    uint32_t sb_ah = smem_u32(as_h), sb_al = smem_u32(as_l);
    uint32_t sb_bh = smem_u32(bs_h), sb_bl = smem_u32(bs_l);

    #pragma unroll
    for (int kc = 0; kc < 128; kc += 64) {
        #pragma unroll
        for (int q = 0; q < 8; q++) {
            int i = q * 256 + tid;
            int r = i >> 4, c4 = i & 15;
            int gr = rowBase + r;
            float4 v = make_float4(0.f, 0.f, 0.f, 0.f);
            if (gr < M) v = *(const float4*)(A + (size_t)gr * 128 + kc + c4 * 4);
            float vv[4] = {v.x, v.y, v.z, v.w};
            int base = r * SA + c4 * 4;
            #pragma unroll
            for (int j = 0; j < 4; j += 2) {
                __nv_bfloat16 h0 = __float2bfloat16_rn(vv[j]);
                __nv_bfloat16 h1 = __float2bfloat16_rn(vv[j + 1]);
                float l0 = vv[j] - __bfloat162float(h0);
                float l1 = vv[j + 1] - __bfloat162float(h1);
                *(__nv_bfloat162*)(as_h + base + j) = __nv_bfloat162(h0, h1);
                *(__nv_bfloat162*)(as_l + base + j) =
                    __nv_bfloat162(__float2bfloat16_rn(l0), __float2bfloat16_rn(l1));
            }
        }
        for (int i = tid; i < 64 * NC8; i += 256) {
            int r = i / NC8, c8 = i % NC8;
            int gi = (kc + r) * NC8 + c8;
            *(uint4*)(bs_h + r * SB + c8 * 8) = ((const uint4*)Bh)[gi];
            *(uint4*)(bs_l + r * SB + c8 * 8) = ((const uint4*)Bl)[gi];
        }
        __syncthreads();

        #pragma unroll
        for (int ks = 0; ks < 4; ks++) {
            int k0 = ks * 16;
            uint32_t ah[2][4], al[2][4];
            #pragma unroll
            for (int mt = 0; mt < 2; mt++) {
                uint32_t off = ((m0 + mt * 16 + lr) * SA + k0 + lc * 8) * 2;
                LDSM_X4(ah[mt][0], ah[mt][1], ah[mt][2], ah[mt][3], sb_ah + off);
                LDSM_X4(al[mt][0], al[mt][1], al[mt][2], al[mt][3], sb_al + off);
            }
            #pragma unroll
            for (int n16 = 0; n16 < NT / 2; n16++) {
                uint32_t off = ((k0 + lr) * SB + n0 + n16 * 16 + lc * 8) * 2;
                uint32_t b0h, b1h, b2h, b3h, b0l, b1l, b2l, b3l;
                LDSM_X4_T(b0h, b1h, b2h, b3h, sb_bh + off);
                LDSM_X4_T(b0l, b1l, b2l, b3l, sb_bl + off);
                int nt0 = 2 * n16, nt1 = 2 * n16 + 1;
                #pragma unroll
                for (int mt = 0; mt < 2; mt++) {
                    mma16816(acc[mt][nt0], ah[mt][0], ah[mt][1], ah[mt][2], ah[mt][3], b0h, b1h);
                    mma16816(acc[mt][nt0], ah[mt][0], ah[mt][1], ah[mt][2], ah[mt][3], b0l, b1l);
                    mma16816(acc[mt][nt0], al[mt][0], al[mt][1], al[mt][2], al[mt][3], b0h, b1h);
                    mma16816(acc[mt][nt1], ah[mt][0], ah[mt][1], ah[mt][2], ah[mt][3], b2h, b3h);
                    mma16816(acc[mt][nt1], ah[mt][0], ah[mt][1], ah[mt][2], ah[mt][3], b2l, b3l);
                    mma16816(acc[mt][nt1], al[mt][0], al[mt][1], al[mt][2], al[mt][3], b2h, b3h);
                }
            }
        }
        __syncthreads();
    }

    int g = lane >> 2, tig = lane & 3;
    #pragma unroll
    for (int mt = 0; mt < 2; mt++) {
        int r0 = rowBase + m0 + mt * 16 + g;
        int r1 = r0 + 8;
        #pragma unroll
        for (int nt = 0; nt < NT; nt++) {
            int col = n0 + nt * 8 + tig * 2;
            if (r0 < M)
                *(__half2*)(H + (size_t)r0 * CN + col) =
                    __floats2half2_rn(acc[mt][nt][0], acc[mt][nt][1]);
            if (r1 < M)
                *(__half2*)(H + (size_t)r1 * CN + col) =
                    __floats2half2_rn(acc[mt][nt][2], acc[mt][nt][3]);
        }
    }

    float sd[2][2] = {}, dd[2][2] = {};
    #pragma unroll
    for (int mt = 0; mt < 2; mt++)
        #pragma unroll
        for (int nt = 0; nt < NT; nt++) {
            int col = n0 + nt * 8 + tig * 2;
            float a0 = __ldg(asrc + col), a1 = __ldg(asrc + col + 1);
            float d0 = __ldg(adst + col), d1 = __ldg(adst + col + 1);
            sd[mt][0] += acc[mt][nt][0] * a0 + acc[mt][nt][1] * a1;
            dd[mt][0] += acc[mt][nt][0] * d0 + acc[mt][nt][1] * d1;
            sd[mt][1] += acc[mt][nt][2] * a0 + acc[mt][nt][3] * a1;
            dd[mt][1] += acc[mt][nt][2] * d0 + acc[mt][nt][3] * d1;
        }
    #pragma unroll
    for (int o = 1; o < 4; o <<= 1) {
        #pragma unroll
        for (int mt = 0; mt < 2; mt++)
            #pragma unroll
            for (int j = 0; j < 2; j++) {
                sd[mt][j] += __shfl_xor_sync(0xffffffffu, sd[mt][j], o);
                dd[mt][j] += __shfl_xor_sync(0xffffffffu, dd[mt][j], o);
            }
    }
    __syncthreads();
    float* red = (float*)smem;
    if (wn == 1 && tig == 0) {
        #pragma unroll
        for (int mt = 0; mt < 2; mt++)
            #pragma unroll
            for (int j = 0; j < 2; j++) {
                int lrow = m0 + mt * 16 + g + j * 8;
                red[lrow] = sd[mt][j];
                red[128 + lrow] = dd[mt][j];
            }
    }
    __syncthreads();
    float hsmax = -3.4e38f;
    if (wn == 0 && tig == 0) {
        #pragma unroll
        for (int mt = 0; mt < 2; mt++)
            #pragma unroll
            for (int j = 0; j < 2; j++) {
                int lrow = m0 + mt * 16 + g + j * 8;
                int gr = rowBase + lrow;
                if (gr < M) {
                    float sv = sd[mt][j] + red[lrow];
                    hs[gr] = sv;
                    hd[gr] = dd[mt][j] + red[128 + lrow];
                    hsmax = fmaxf(hsmax, sv);
                }
            }
    }
    #pragma unroll
    for (int o = 16; o; o >>= 1)
        hsmax = fmaxf(hsmax, __shfl_xor_sync(0xffffffffu, hsmax, o));
    if (wn == 0 && lane == 0) atomicMax(gmax, fkey(hsmax));
}

// ---------------------------------------------------------------------------
__device__ __forceinline__ float leaky02(float a) {
    return a > 0.f ? a : 0.2f * a;
}

// warp-per-node single-pass GAT aggregation; loop_attr computed inline.
template <int C>
__global__ void __launch_bounds__(256)
gat_agg_k(const __half* __restrict__ h, const float* __restrict__ hs,
          const float* __restrict__ hd, const int* __restrict__ offs,
          const float2* __restrict__ csre,
          const float* __restrict__ bias,
          const float* __restrict__ cptr, const unsigned* __restrict__ gmax,
          float* __restrict__ xout, int n) {
    constexpr int VL = C / 32;
    int w = (blockIdx.x * blockDim.x + threadIdx.x) >> 5;
    if (w >= n) return;
    int lane = threadIdx.x & 31;
    float c = *cptr;
    float hdn = hd[w];
    float ub = leaky02(funkey(*gmax) + hdn + fmaxf(c, 0.f));
    int beg = offs[w], end = offs[w + 1];

    float acc[VL];
    #pragma unroll
    for (int j = 0; j < VL; j++) acc[j] = 0.f;
    float denom = 0.f;
    float colsum = 0.f;               // warp-uniform: every lane reads same edges
    const size_t loff = (size_t)lane * VL;

    int e = beg;
    for (; e + 4 <= end; e += 4) {
        float2 p0 = csre[e], p1 = csre[e + 1], p2 = csre[e + 2], p3 = csre[e + 3];
        int s0 = __float_as_int(p0.x), s1 = __float_as_int(p1.x);
        int s2 = __float_as_int(p2.x), s3 = __float_as_int(p3.x);
        colsum += (p0.y + p1.y) + (p2.y + p3.y);
        float ex0 = __expf(leaky02(hs[s0] + hdn + p0.y * c) - ub);
        float ex1 = __expf(leaky02(hs[s1] + hdn + p1.y * c) - ub);
        float ex2 = __expf(leaky02(hs[s2] + hdn + p2.y * c) - ub);
        float ex3 = __expf(leaky02(hs[s3] + hdn + p3.y * c) - ub);
        denom += (ex0 + ex1) + (ex2 + ex3);
        if (VL == 4) {
            uint2 r0 = *(const uint2*)(h + (size_t)s0 * C + loff);
            uint2 r1 = *(const uint2*)(h + (size_t)s1 * C + loff);
            uint2 r2 = *(const uint2*)(h + (size_t)s2 * C + loff);
            uint2 r3 = *(const uint2*)(h + (size_t)s3 * C + loff);
            float2 a0 = __half22float2(*(__half2*)&r0.x), b0 = __half22float2(*(__half2*)&r0.y);
            float2 a1 = __half22float2(*(__half2*)&r1.x), b1 = __half22float2(*(__half2*)&r1.y);
            float2 a2 = __half22float2(*(__half2*)&r2.x), b2 = __half22float2(*(__half2*)&r2.y);
            float2 a3 = __half22float2(*(__half2*)&r3.x), b3 = __half22float2(*(__half2*)&r3.y);
            acc[0] += ex0 * a0.x + ex1 * a1.x + ex2 * a2.x + ex3 * a3.x;
            acc[1] += ex0 * a0.y + ex1 * a1.y + ex2 * a2.y + ex3 * a3.y;
            acc[2] += ex0 * b0.x + ex1 * b1.x + ex2 * b2.x + ex3 * b3.x;
            acc[3] += ex0 * b0.y + ex1 * b1.y + ex2 * b2.y + ex3 * b3.y;
        } else {
            float2 v0 = __half22float2(*(const __half2*)(h + (size_t)s0 * C + loff));
            float2 v1 = __half22float2(*(const __half2*)(h + (size_t)s1 * C + loff));
            float2 v2 = __half22float2(*(const __half2*)(h + (size_t)s2 * C + loff));
            float2 v3 = __half22float2(*(const __half2*)(h + (size_t)s3 * C + loff));
            acc[0] += ex0 * v0.x + ex1 * v1.x + ex2 * v2.x + ex3 * v3.x;
            acc[1] += ex0 * v0.y + ex1 * v1.y + ex2 * v2.y + ex3 * v3.y;
        }
    }
    for (; e < end; e++) {
        float2 p = csre[e];
        int s = __float_as_int(p.x);
        colsum += p.y;
        float ex = __expf(leaky02(hs[s] + hdn + p.y * c) - ub);
        denom += ex;
        if (VL == 4) {
            uint2 r = *(const uint2*)(h + (size_t)s * C + loff);
            float2 a = __half22float2(*(__half2*)&r.x), b = __half22float2(*(__half2*)&r.y);
            acc[0] += ex * a.x; acc[1] += ex * a.y;
            acc[2] += ex * b.x; acc[3] += ex * b.y;
        } else {
            float2 v = __half22float2(*(const __half2*)(h + (size_t)s * C + loff));
            acc[0] += ex * v.x; acc[1] += ex * v.y;
        }
    }
    {   // self loop: loop_attr = colsum / max(deg,1)
        int deg = end - beg;
        float lattr = colsum / (float)(deg > 1 ? deg : 1);
        float aself = leaky02(hs[w] + hdn + lattr * c);
        float ex = __expf(aself - ub);
        denom += ex;
        if (VL == 4) {
            uint2 r = *(const uint2*)(h + (size_t)w * C + loff);
            float2 a = __half22float2(*(__half2*)&r.x), b = __half22float2(*(__half2*)&r.y);
            acc[0] += ex * a.x; acc[1] += ex * a.y;
            acc[2] += ex * b.x; acc[3] += ex * b.y;
        } else {
            float2 v = __half22float2(*(const __half2*)(h + (size_t)w * C + loff));
            acc[0] += ex * v.x; acc[1] += ex * v.y;
        }
    }
    float inv = 1.f / denom;
    float out[VL];
    #pragma unroll
    for (int j = 0; j < VL; j++) {
        float v = acc[j] * inv + bias[loff + j];
        out[j] = v > 0.f ? v : expm1f(v);
    }
    float* xr = xout + (size_t)w * C + loff;
    if (VL == 4) *(float4*)xr = make_float4(out[0], out[1], out[2], out[3]);
    else         *(float2*)xr = make_float2(out[0], out[1]);
}

__global__ void colsum_k(const float* __restrict__ x, float* g, int n) {
    int c = threadIdx.x;
    float s = 0.f;
    for (int r = blockIdx.x; r < n; r += gridDim.x) s += x[(size_t)r * 64 + c];
    atomicAdd(&g[c], s);
}

__global__ void head_k(const float* __restrict__ g, const float* __restrict__ xn1,
                       const float* __restrict__ xn2, const float* __restrict__ Wlin,
                       const float* __restrict__ blin, const float* __restrict__ Wc1,
                       const float* __restrict__ bc1, const float* __restrict__ Wc2,
                       const float* __restrict__ bc2, float* __restrict__ out, int n) {
    __shared__ float v[128];
    __shared__ float hh[16];
    int t = threadIdx.x;
    int gi = t >> 6, c = t & 63;
    const float* gg = g + gi * 64;
    const float* xn = gi ? xn2 : xn1;
    float inv = 1.f / (float)n;
    float s = blin[c];
    for (int k = 0; k < 64; k++) s += (gg[k] * inv) * Wlin[k * 64 + c];
    for (int k = 0; k < 16; k++) s += xn[k] * Wlin[(64 + k) * 64 + c];
    v[t] = s;
    __syncthreads();
    if (t < 16) {
        float a = bc1[t];
        for (int k = 0; k < 128; k++) a += v[k] * Wc1[k * 16 + t];
        hh[t] = fmaxf(a, 0.f);
    }
    __syncthreads();
    if (t < 3) {
        float a = bc2[t];
        for (int k = 0; k < 16; k++) a += hh[k] * Wc2[k * 3 + t];
        out[t] = a;
    }
}

// ---------------------------------------------------------------------------
extern "C" void kernel_launch(void* const* d_in, const int* in_sizes, int n_in,
                              void* d_out, int out_size) {
    const int IN = 7;
    const int N = in_sizes[0] / IN;
    const int E = in_sizes[2] / 2;

    static cudaStream_t s1 = nullptr, sCsr = nullptr;
    static cudaEvent_t evF = nullptr, evP = nullptr, evC = nullptr, evJ = nullptr;
    if (!s1) {
        cudaStreamCreateWithFlags(&s1, cudaStreamNonBlocking);
        cudaStreamCreateWithFlags(&sCsr, cudaStreamNonBlocking);
        cudaEventCreateWithFlags(&evF, cudaEventDisableTiming);
        cudaEventCreateWithFlags(&evP, cudaEventDisableTiming);
        cudaEventCreateWithFlags(&evC, cudaEventDisableTiming);
        cudaEventCreateWithFlags(&evJ, cudaEventDisableTiming);
        cudaFuncSetAttribute(gemm_mma_k<128>,
                             cudaFuncAttributeMaxDynamicSharedMemorySize, 71680);
        cudaFuncSetAttribute(gemm_mma_k<64>,
                             cudaFuncAttributeMaxDynamicSharedMemorySize, 55296);
    }

    float *b_x, *b_hs, *b_hd, *p_g, *b_c;
    float2* b_csre;
    __half* b_hh;
    unsigned* b_max;
    int *b_deg, *b_offs, *b_cursor, *b_tsum;
    __nv_bfloat16 *b_wbh, *b_wbl;
    cudaGetSymbolAddress((void**)&b_hh, g_hh);
    cudaGetSymbolAddress((void**)&b_x, g_x);
    cudaGetSymbolAddress((void**)&b_hs, g_hs);
    cudaGetSymbolAddress((void**)&b_hd, g_hd);
    cudaGetSymbolAddress((void**)&b_csre, g_csre);
    cudaGetSymbolAddress((void**)&p_g, g_gvec);
    cudaGetSymbolAddress((void**)&b_c, g_c);
    cudaGetSymbolAddress((void**)&b_max, g_maxhs);
    cudaGetSymbolAddress((void**)&b_deg, g_deg);
    cudaGetSymbolAddress((void**)&b_offs, g_offs);
    cudaGetSymbolAddress((void**)&b_cursor, g_cursor);
    cudaGetSymbolAddress((void**)&b_tsum, g_tsum);
    cudaGetSymbolAddress((void**)&b_wbh, g_wbh);
    cudaGetSymbolAddress((void**)&b_wbl, g_wbl);

    const float* x_in[2]  = {(const float*)d_in[0], (const float*)d_in[1]};
    const int*   ei[2]    = {(const int*)d_in[2], (const int*)d_in[3]};
    const float* xnorm[2] = {(const float*)d_in[4], (const float*)d_in[5]};
    const float* ecol[2]  = {(const float*)d_in[6], (const float*)d_in[7]};

    const float* W[3]; const float* asrc[3]; const float* adst[3];
    const float* We[3]; const float* ae[3]; const float* bb[3];
    for (int l = 0; l < 3; l++) {
        W[l]    = (const float*)d_in[8 + 6 * l + 0];
        asrc[l] = (const float*)d_in[8 + 6 * l + 1];
        adst[l] = (const float*)d_in[8 + 6 * l + 2];
        We[l]   = (const float*)d_in[8 + 6 * l + 3];
        ae[l]   = (const float*)d_in[8 + 6 * l + 4];
        bb[l]   = (const float*)d_in[8 + 6 * l + 5];
    }
    const float* Wlin = (const float*)d_in[26];
    const float* blin = (const float*)d_in[27];
    const float* Wc1  = (const float*)d_in[28];
    const float* bc1  = (const float*)d_in[29];
    const float* Wc2  = (const float*)d_in[30];
    const float* bc2  = (const float*)d_in[31];

    const int eHalfBlocks = (E + 255) / 256;        // 2 edges/thread, 2 graphs
    const int nT = (N + TILE - 1) / TILE;
    const int tcBlocks = (N + 127) / 128;
    const int g7Blocks = (N + 7) / 8;
    const int aggBlocks = (N * 32 + 255) / 256;

    // fork point: all side streams branch from stream 0 (capture-legal)
    cudaEventRecord(evF, 0);
    cudaStreamWaitEvent(sCsr, evF, 0);
    cudaStreamWaitEvent(s1, evF, 0);

    // batched CSR build on side stream
    cudaMemsetAsync(b_deg, 0, 2 * MAX_N * sizeof(int), sCsr);
    build_deg_k<<<eHalfBlocks, 256, 0, sCsr>>>(ei[0], ei[1], b_deg, E);
    scan1_k<<<2 * nT, 256, 0, sCsr>>>(b_deg, b_tsum, N, nT);
    scan2_k<<<1, 256, 0, sCsr>>>(b_tsum, nT);
    scan3_k<<<2 * nT, TILE, 0, sCsr>>>(b_deg, b_tsum, b_offs, b_cursor, N, nT);
    scatter_k<<<eHalfBlocks, 256, 0, sCsr>>>(ei[0], ecol[0], ei[1], ecol[1],
                                             b_cursor, b_csre, E);
    cudaEventRecord(evC, sCsr);

    // prologue on stream 0 (graph-invariant), concurrent with CSR
    cudaMemsetAsync(p_g, 0, 128 * sizeof(float), 0);
    cudaMemsetAsync(b_max, 0, 6 * sizeof(unsigned), 0);
    wsplit_k<<<(128 * 128 + 255) / 256, 256, 0, 0>>>(W[1], b_wbh, b_wbl, 128 * 128);
    wsplit_k<<<(128 * 64 + 255) / 256, 256, 0, 0>>>(W[2], b_wbh + 128 * 128,
                                                    b_wbl + 128 * 128, 128 * 64);
    cscalar3_k<<<1, 96, 0, 0>>>(We[0], ae[0], We[1], ae[1], We[2], ae[2], b_c);
    cudaEventRecord(evP, 0);
    cudaStreamWaitEvent(s1, evP, 0);

    // per-graph chains on two streams
    for (int gph = 0; gph < 2; gph++) {
        cudaStream_t st = gph ? s1 : (cudaStream_t)0;
        __half* p_hh = b_hh + (size_t)gph * MAX_N * 128;
        float* p_x = b_x + (size_t)gph * MAX_N * 128;
        float* p_hs = b_hs + gph * MAX_N;
        float* p_hd = b_hd + gph * MAX_N;
        float2* p_csre = b_csre + (size_t)gph * MAX_E;
        int* p_offs = b_offs + gph * (MAX_N + 1);

        gemm7_k<<<g7Blocks, 256, 0, st>>>(x_in[gph], W[0], asrc[0], adst[0],
                                          p_hh, p_hs, p_hd, b_max + 0 + gph, N);
        cudaStreamWaitEvent(st, evC, 0);

        gat_agg_k<128><<<aggBlocks, 256, 0, st>>>(p_hh, p_hs, p_hd, p_offs, p_csre,
                                                  bb[0], b_c + 0,
                                                  b_max + 0 + gph, p_x, N);
        gemm_mma_k<128><<<tcBlocks, 256, 71680, st>>>(
            p_x, b_wbh, b_wbl, asrc[1], adst[1], p_hh, p_hs, p_hd,
            b_max + 2 + gph, N);
        gat_agg_k<128><<<aggBlocks, 256, 0, st>>>(p_hh, p_hs, p_hd, p_offs, p_csre,
                                                  bb[1], b_c + 1,
                                                  b_max + 2 + gph, p_x, N);
        gemm_mma_k<64><<<tcBlocks, 256, 55296, st>>>(
            p_x, b_wbh + 128 * 128, b_wbl + 128 * 128, asrc[2], adst[2],
            p_hh, p_hs, p_hd, b_max + 4 + gph, N);
        gat_agg_k<64><<<aggBlocks, 256, 0, st>>>(p_hh, p_hs, p_hd, p_offs, p_csre,
                                                 bb[2], b_c + 2,
                                                 b_max + 4 + gph, p_x, N);
        colsum_k<<<512, 64, 0, st>>>(p_x, p_g + gph * 64, N);
    }

    cudaEventRecord(evJ, s1);
    cudaStreamWaitEvent((cudaStream_t)0, evJ, 0);
    head_k<<<1, 128, 0, 0>>>(p_g, xnorm[0], xnorm[1], Wlin, blin, Wc1, bc1, Wc2, bc2,
                             (float*)d_out, N);
}

// round 13
// speedup vs baseline: 1.0664x; 1.0664x over previous
#include <cuda_runtime.h>
#include <cuda_bf16.h>
#include <cuda_fp16.h>
#include <math.h>
#include <stdint.h>

// ---------------------------------------------------------------------------
// SpatialModel: 3-layer GATConv on two graphs (N=50000, E=800000), mean pool,
// MLP head -> [1,3] logits.
//
// R13: agg main loop unrolled x8 (deeper MLP), mean-pool fused into layer-2
// aggregation (x write + colsum read + 2 launches removed). Otherwise R12:
// two-stream per-graph pipeline, batched CSR on side stream, fp16 h payload,
// single-pass softmax via global ub shift, K-chunked bf16-split mma GEMMs.
// ---------------------------------------------------------------------------

#define MAX_N 50000
#define MAX_E 800000
#define TILE 512

__device__ __align__(16) __half g_hh[2][MAX_N * 128];
__device__ float g_x[2][MAX_N * 128];
__device__ float g_hs[2][MAX_N];
__device__ float g_hd[2][MAX_N];
__device__ int   g_deg[2][MAX_N];
__device__ int   g_offs[2][MAX_N + 1];
__device__ int   g_cursor[2][MAX_N];
__device__ __align__(16) float2 g_csre[2][MAX_E];
__device__ int   g_tsum[2][128];
__device__ float g_c[3];
__device__ unsigned g_maxhs[6];     // [layer*2 + graph]
__device__ float g_gvec[128];
__device__ __align__(16) __nv_bfloat16 g_wbh[2][128 * 128];
__device__ __align__(16) __nv_bfloat16 g_wbl[2][128 * 128];

// ---------------------------------------------------------------------------
__device__ __forceinline__ uint32_t smem_u32(const void* p) {
    uint32_t a;
    asm("{ .reg .u64 t; cvta.to.shared.u64 t, %1; cvt.u32.u64 %0, t; }"
        : "=r"(a) : "l"(p));
    return a;
}
__device__ __forceinline__ unsigned fkey(float f) {
    int i = __float_as_int(f);
    return i >= 0 ? ((unsigned)i | 0x80000000u) : ~(unsigned)i;
}
__device__ __forceinline__ float funkey(unsigned k) {
    return (k & 0x80000000u) ? __int_as_float((int)(k & 0x7FFFFFFFu))
                             : __int_as_float((int)~k);
}
#define LDSM_X4(r0, r1, r2, r3, addr)                                          \
    asm volatile("ldmatrix.sync.aligned.m8n8.x4.shared.b16 {%0,%1,%2,%3}, [%4];" \
                 : "=r"(r0), "=r"(r1), "=r"(r2), "=r"(r3) : "r"(addr))
#define LDSM_X4_T(r0, r1, r2, r3, addr)                                        \
    asm volatile("ldmatrix.sync.aligned.m8n8.x4.trans.shared.b16 {%0,%1,%2,%3}, [%4];" \
                 : "=r"(r0), "=r"(r1), "=r"(r2), "=r"(r3) : "r"(addr))
__device__ __forceinline__ void mma16816(float* c, uint32_t a0, uint32_t a1,
                                         uint32_t a2, uint32_t a3,
                                         uint32_t b0, uint32_t b1) {
    asm volatile(
        "mma.sync.aligned.m16n8k16.row.col.f32.bf16.bf16.f32 "
        "{%0,%1,%2,%3}, {%4,%5,%6,%7}, {%8,%9}, {%0,%1,%2,%3};"
        : "+f"(c[0]), "+f"(c[1]), "+f"(c[2]), "+f"(c[3])
        : "r"(a0), "r"(a1), "r"(a2), "r"(a3), "r"(b0), "r"(b1));
}

// ---------------------------------------------------------------------------
__global__ void build_deg_k(const int* __restrict__ ei0, const int* __restrict__ ei1,
                            int* deg, int E) {
    int i = (blockIdx.x * blockDim.x + threadIdx.x) * 2;
    if (i >= 2 * E) return;
    int g = (i >= E);
    int j = i - g * E;
    const int* dst = (g ? ei1 : ei0) + E;
    int d0 = dst[j];
    int d1 = dst[j + 1];
    atomicAdd(&deg[g * MAX_N + d0], 1);
    atomicAdd(&deg[g * MAX_N + d1], 1);
}

__global__ void scan1_k(const int* __restrict__ deg, int* tsum, int n, int nT) {
    __shared__ int sh[256];
    int bx = blockIdx.x, t = threadIdx.x;
    int g = (bx >= nT);
    int b = bx - g * nT;
    const int* dg = deg + g * MAX_N;
    int i0 = b * TILE;
    int s = 0;
    int i = i0 + t;        if (i < n) s += dg[i];
    i = i0 + 256 + t;      if (i < n) s += dg[i];
    sh[t] = s;
    __syncthreads();
    for (int o = 128; o; o >>= 1) { if (t < o) sh[t] += sh[t + o]; __syncthreads(); }
    if (t == 0) tsum[g * 128 + b] = sh[0];
}
__global__ void scan2_k(int* tsum, int nT) {
    __shared__ int sh[256];
    int t = threadIdx.x;
    int g = t >> 7, tl = t & 127;
    int v0 = (tl < nT) ? tsum[g * 128 + tl] : 0;
    sh[t] = v0;
    __syncthreads();
    for (int d = 1; d < 128; d <<= 1) {
        int v = (tl >= d) ? sh[t - d] : 0;
        __syncthreads();
        sh[t] += v;
        __syncthreads();
    }
    if (tl < nT) tsum[g * 128 + tl] = sh[t] - v0;
}
__global__ void scan3_k(const int* __restrict__ deg, const int* __restrict__ tsum,
                        int* offs, int* cursor, int n, int nT) {
    __shared__ int sh[TILE];
    int bx = blockIdx.x, t = threadIdx.x;
    int g = (bx >= nT);
    int b = bx - g * nT;
    const int* dg = deg + g * MAX_N;
    const int* ts = tsum + g * 128;
    int* of = offs + g * (MAX_N + 1);
    int* cu = cursor + g * MAX_N;
    int i = b * TILE + t;
    int d = (i < n) ? dg[i] : 0;
    sh[t] = d;
    __syncthreads();
    for (int o = 1; o < TILE; o <<= 1) {
        int v = (t >= o) ? sh[t - o] : 0;
        __syncthreads();
        sh[t] += v;
        __syncthreads();
    }
    if (i < n) {
        int base = ts[b];
        int off = base + sh[t] - d;
        of[i] = off;
        cu[i] = off;
        if (i == n - 1) of[n] = base + sh[t];
    }
}

__global__ void scatter_k(const int* __restrict__ ei0, const float* __restrict__ col0,
                          const int* __restrict__ ei1, const float* __restrict__ col1,
                          int* cursor, float2* csre, int E) {
    int i = (blockIdx.x * blockDim.x + threadIdx.x) * 2;
    if (i >= 2 * E) return;
    int g = (i >= E);
    int j = i - g * E;
    const int* ei = g ? ei1 : ei0;
    const float* col = g ? col1 : col0;
    int* cur = cursor + g * MAX_N;
    float2* cs = csre + (size_t)g * MAX_E;
    int s0 = ei[j], s1 = ei[j + 1];
    int d0 = ei[E + j], d1 = ei[E + j + 1];
    float c0 = col[j], c1 = col[j + 1];
    int p0 = atomicAdd(&cur[d0], 1);
    int p1 = atomicAdd(&cur[d1], 1);
    cs[p0] = make_float2(__int_as_float(s0), c0);
    cs[p1] = make_float2(__int_as_float(s1), c1);
}

// ---------------------------------------------------------------------------
__global__ void wsplit_k(const float* __restrict__ W, __nv_bfloat16* hi,
                         __nv_bfloat16* lo, int n) {
    int i = blockIdx.x * blockDim.x + threadIdx.x;
    if (i >= n) return;
    float v = W[i];
    __nv_bfloat16 h = __float2bfloat16_rn(v);
    hi[i] = h;
    lo[i] = __float2bfloat16_rn(v - __bfloat162float(h));
}

__global__ void cscalar3_k(const float* __restrict__ We1, const float* __restrict__ ae1,
                           const float* __restrict__ We2, const float* __restrict__ ae2,
                           const float* __restrict__ We3, const float* __restrict__ ae3,
                           float* out) {
    int w = threadIdx.x >> 5, lane = threadIdx.x & 31;
    if (w >= 3) return;
    const float* We = (w == 0) ? We1 : (w == 1) ? We2 : We3;
    const float* ae = (w == 0) ? ae1 : (w == 1) ? ae2 : ae3;
    int C = (w == 2) ? 64 : 128;
    float s = 0.f;
    for (int k = lane; k < C; k += 32) s += We[k] * ae[k];
    #pragma unroll
    for (int o = 16; o; o >>= 1) s += __shfl_xor_sync(0xffffffffu, s, o);
    if (lane == 0) out[w] = s;
}

// ---------------------------------------------------------------------------
__global__ void __launch_bounds__(256)
gemm7_k(const float* __restrict__ x, const float* __restrict__ W,
        const float* __restrict__ asrc, const float* __restrict__ adst,
        __half* __restrict__ h, float* __restrict__ hs, float* __restrict__ hd,
        unsigned* __restrict__ gmax, int M) {
    __shared__ float Ws[7 * 128], As[128], Ad[128];
    __shared__ float wmax[8];
    int t = threadIdx.x;
    for (int i = t; i < 7 * 128; i += 256) Ws[i] = W[i];
    if (t < 128) { As[t] = asrc[t]; Ad[t] = adst[t]; }
    __syncthreads();
    int r = blockIdx.x * 8 + (t >> 5);
    bool active = (r < M);
    int lane = t & 31, c0 = lane * 4;
    float s = 0.f, d = 0.f;
    if (active) {
        float xv[7];
        #pragma unroll
        for (int k = 0; k < 7; k++) xv[k] = x[(size_t)r * 7 + k];
        float out[4];
        #pragma unroll
        for (int j = 0; j < 4; j++) {
            float acc = 0.f;
            #pragma unroll
            for (int k = 0; k < 7; k++) acc += xv[k] * Ws[k * 128 + c0 + j];
            out[j] = acc;
        }
        __half2 p0 = __floats2half2_rn(out[0], out[1]);
        __half2 p1 = __floats2half2_rn(out[2], out[3]);
        uint2 u = make_uint2(*(uint32_t*)&p0, *(uint32_t*)&p1);
        *(uint2*)(h + (size_t)r * 128 + c0) = u;
        s = out[0] * As[c0] + out[1] * As[c0 + 1] + out[2] * As[c0 + 2] + out[3] * As[c0 + 3];
        d = out[0] * Ad[c0] + out[1] * Ad[c0 + 1] + out[2] * Ad[c0 + 2] + out[3] * Ad[c0 + 3];
        #pragma unroll
        for (int o = 16; o; o >>= 1) {
            s += __shfl_xor_sync(0xffffffffu, s, o);
            d += __shfl_xor_sync(0xffffffffu, d, o);
        }
        if (lane == 0) { hs[r] = s; hd[r] = d; }
    }
    if (lane == 0) wmax[t >> 5] = active ? s : -3.4e38f;
    __syncthreads();
    if (t == 0) {
        float m = wmax[0];
        #pragma unroll
        for (int i = 1; i < 8; i++) m = fmaxf(m, wmax[i]);
        atomicMax(gmax, fkey(m));
    }
}

// ---------------------------------------------------------------------------
template <int CN>
__global__ void __launch_bounds__(256, 2)
gemm_mma_k(const float* __restrict__ A, const __nv_bfloat16* __restrict__ Bh,
           const __nv_bfloat16* __restrict__ Bl,
           const float* __restrict__ asrc, const float* __restrict__ adst,
           __half* __restrict__ H, float* __restrict__ hs, float* __restrict__ hd,
           unsigned* __restrict__ gmax, int M) {
    extern __shared__ char smem[];
    constexpr int SA = 72;
    constexpr int SB = CN + 8;
    constexpr int AH = 0;
    constexpr int AL = 128 * SA * 2;
    constexpr int BH = 2 * AL;
    constexpr int BL = BH + 64 * SB * 2;
    constexpr int NT = CN / 16;
    constexpr int NC8 = CN / 8;

    int tid = threadIdx.x, lane = tid & 31, warp = tid >> 5;
    const int rowBase = blockIdx.x * 128;

    __nv_bfloat16* as_h = (__nv_bfloat16*)(smem + AH);
    __nv_bfloat16* as_l = (__nv_bfloat16*)(smem + AL);
    __nv_bfloat16* bs_h = (__nv_bfloat16*)(smem + BH);
    __nv_bfloat16* bs_l = (__nv_bfloat16*)(smem + BL);

    int wm = warp >> 1, wn = warp & 1;
    int m0 = wm * 32, n0 = wn * (CN / 2);

    float acc[2][NT][4];
    #pragma unroll
    for (int a = 0; a < 2; a++)
        #pragma unroll
        for (int b = 0; b < NT; b++)
            #pragma unroll
            for (int q = 0; q < 4; q++) acc[a][b][q] = 0.f;

    int lr = lane & 15, lc = lane >> 4;
    uint32_t sb_ah = smem_u32(as_h), sb_al = smem_u32(as_l);
    uint32_t sb_bh = smem_u32(bs_h), sb_bl = smem_u32(bs_l);

    #pragma unroll
    for (int kc = 0; kc < 128; kc += 64) {
        #pragma unroll
        for (int q = 0; q < 8; q++) {
            int i = q * 256 + tid;
            int r = i >> 4, c4 = i & 15;
            int gr = rowBase + r;
            float4 v = make_float4(0.f, 0.f, 0.f, 0.f);
            if (gr < M) v = *(const float4*)(A + (size_t)gr * 128 + kc + c4 * 4);
            float vv[4] = {v.x, v.y, v.z, v.w};
            int base = r * SA + c4 * 4;
            #pragma unroll
            for (int j = 0; j < 4; j += 2) {
                __nv_bfloat16 h0 = __float2bfloat16_rn(vv[j]);
                __nv_bfloat16 h1 = __float2bfloat16_rn(vv[j + 1]);
                float l0 = vv[j] - __bfloat162float(h0);
                float l1 = vv[j + 1] - __bfloat162float(h1);
                *(__nv_bfloat162*)(as_h + base + j) = __nv_bfloat162(h0, h1);
                *(__nv_bfloat162*)(as_l + base + j) =
                    __nv_bfloat162(__float2bfloat16_rn(l0), __float2bfloat16_rn(l1));
            }
        }
        for (int i = tid; i < 64 * NC8; i += 256) {
            int r = i / NC8, c8 = i % NC8;
            int gi = (kc + r) * NC8 + c8;
            *(uint4*)(bs_h + r * SB + c8 * 8) = ((const uint4*)Bh)[gi];
            *(uint4*)(bs_l + r * SB + c8 * 8) = ((const uint4*)Bl)[gi];
        }
        __syncthreads();

        #pragma unroll
        for (int ks = 0; ks < 4; ks++) {
            int k0 = ks * 16;
            uint32_t ah[2][4], al[2][4];
            #pragma unroll
            for (int mt = 0; mt < 2; mt++) {
                uint32_t off = ((m0 + mt * 16 + lr) * SA + k0 + lc * 8) * 2;
                LDSM_X4(ah[mt][0], ah[mt][1], ah[mt][2], ah[mt][3], sb_ah + off);
                LDSM_X4(al[mt][0], al[mt][1], al[mt][2], al[mt][3], sb_al + off);
            }
            #pragma unroll
            for (int n16 = 0; n16 < NT / 2; n16++) {
                uint32_t off = ((k0 + lr) * SB + n0 + n16 * 16 + lc * 8) * 2;
                uint32_t b0h, b1h, b2h, b3h, b0l, b1l, b2l, b3l;
                LDSM_X4_T(b0h, b1h, b2h, b3h, sb_bh + off);
                LDSM_X4_T(b0l, b1l, b2l, b3l, sb_bl + off);
                int nt0 = 2 * n16, nt1 = 2 * n16 + 1;
                #pragma unroll
                for (int mt = 0; mt < 2; mt++) {
                    mma16816(acc[mt][nt0], ah[mt][0], ah[mt][1], ah[mt][2], ah[mt][3], b0h, b1h);
                    mma16816(acc[mt][nt0], ah[mt][0], ah[mt][1], ah[mt][2], ah[mt][3], b0l, b1l);
                    mma16816(acc[mt][nt0], al[mt][0], al[mt][1], al[mt][2], al[mt][3], b0h, b1h);
                    mma16816(acc[mt][nt1], ah[mt][0], ah[mt][1], ah[mt][2], ah[mt][3], b2h, b3h);
                    mma16816(acc[mt][nt1], ah[mt][0], ah[mt][1], ah[mt][2], ah[mt][3], b2l, b3l);
                    mma16816(acc[mt][nt1], al[mt][0], al[mt][1], al[mt][2], al[mt][3], b2h, b3h);
                }
            }
        }
        __syncthreads();
    }

    int g = lane >> 2, tig = lane & 3;
    #pragma unroll
    for (int mt = 0; mt < 2; mt++) {
        int r0 = rowBase + m0 + mt * 16 + g;
        int r1 = r0 + 8;
        #pragma unroll
        for (int nt = 0; nt < NT; nt++) {
            int col = n0 + nt * 8 + tig * 2;
            if (r0 < M)
                *(__half2*)(H + (size_t)r0 * CN + col) =
                    __floats2half2_rn(acc[mt][nt][0], acc[mt][nt][1]);
            if (r1 < M)
                *(__half2*)(H + (size_t)r1 * CN + col) =
                    __floats2half2_rn(acc[mt][nt][2], acc[mt][nt][3]);
        }
    }

    float sd[2][2] = {}, dd[2][2] = {};
    #pragma unroll
    for (int mt = 0; mt < 2; mt++)
        #pragma unroll
        for (int nt = 0; nt < NT; nt++) {
            int col = n0 + nt * 8 + tig * 2;
            float a0 = __ldg(asrc + col), a1 = __ldg(asrc + col + 1);
            float d0 = __ldg(adst + col), d1 = __ldg(adst + col + 1);
            sd[mt][0] += acc[mt][nt][0] * a0 + acc[mt][nt][1] * a1;
            dd[mt][0] += acc[mt][nt][0] * d0 + acc[mt][nt][1] * d1;
            sd[mt][1] += acc[mt][nt][2] * a0 + acc[mt][nt][3] * a1;
            dd[mt][1] += acc[mt][nt][2] * d0 + acc[mt][nt][3] * d1;
        }
    #pragma unroll
    for (int o = 1; o < 4; o <<= 1) {
        #pragma unroll
        for (int mt = 0; mt < 2; mt++)
            #pragma unroll
            for (int j = 0; j < 2; j++) {
                sd[mt][j] += __shfl_xor_sync(0xffffffffu, sd[mt][j], o);
                dd[mt][j] += __shfl_xor_sync(0xffffffffu, dd[mt][j], o);
            }
    }
    __syncthreads();
    float* red = (float*)smem;
    if (wn == 1 && tig == 0) {
        #pragma unroll
        for (int mt = 0; mt < 2; mt++)
            #pragma unroll
            for (int j = 0; j < 2; j++) {
                int lrow = m0 + mt * 16 + g + j * 8;
                red[lrow] = sd[mt][j];
                red[128 + lrow] = dd[mt][j];
            }
    }
    __syncthreads();
    float hsmax = -3.4e38f;
    if (wn == 0 && tig == 0) {
        #pragma unroll
        for (int mt = 0; mt < 2; mt++)
            #pragma unroll
            for (int j = 0; j < 2; j++) {
                int lrow = m0 + mt * 16 + g + j * 8;
                int gr = rowBase + lrow;
                if (gr < M) {
                    float sv = sd[mt][j] + red[lrow];
                    hs[gr] = sv;
                    hd[gr] = dd[mt][j] + red[128 + lrow];
                    hsmax = fmaxf(hsmax, sv);
                }
            }
    }
    #pragma unroll
    for (int o = 16; o; o >>= 1)
        hsmax = fmaxf(hsmax, __shfl_xor_sync(0xffffffffu, hsmax, o));
    if (wn == 0 && lane == 0) atomicMax(gmax, fkey(hsmax));
}

// ---------------------------------------------------------------------------
__device__ __forceinline__ float leaky02(float a) {
    return a > 0.f ? a : 0.2f * a;
}

// warp-per-node single-pass GAT aggregation; loop_attr inline; unroll x8.
// POOL: skip x write, accumulate block-level mean-pool partials into gsum.
template <int C, bool POOL>
__global__ void __launch_bounds__(256)
gat_agg_k(const __half* __restrict__ h, const float* __restrict__ hs,
          const float* __restrict__ hd, const int* __restrict__ offs,
          const float2* __restrict__ csre,
          const float* __restrict__ bias,
          const float* __restrict__ cptr, const unsigned* __restrict__ gmax,
          float* __restrict__ xout, float* __restrict__ gsum, int n) {
    constexpr int VL = C / 32;
    __shared__ float sums[64];
    int w = (blockIdx.x * blockDim.x + threadIdx.x) >> 5;
    int lane = threadIdx.x & 31;
    bool active = (w < n);

    if (POOL) {
        if (threadIdx.x < 64) sums[threadIdx.x] = 0.f;
        __syncthreads();
    }

    float out[VL];
    if (active) {
        float c = *cptr;
        float hdn = hd[w];
        float ub = leaky02(funkey(*gmax) + hdn + fmaxf(c, 0.f));
        int beg = offs[w], end = offs[w + 1];

        float acc[VL];
        #pragma unroll
        for (int j = 0; j < VL; j++) acc[j] = 0.f;
        float denom = 0.f;
        float colsum = 0.f;
        const size_t loff = (size_t)lane * VL;

        int e = beg;
        // x8 unrolled main loop (deep MLP)
        for (; e + 8 <= end; e += 8) {
            float2 p[8]; int s[8]; float ex[8];
            #pragma unroll
            for (int q = 0; q < 8; q++) p[q] = csre[e + q];
            #pragma unroll
            for (int q = 0; q < 8; q++) {
                s[q] = __float_as_int(p[q].x);
                colsum += p[q].y;
            }
            #pragma unroll
            for (int q = 0; q < 8; q++) {
                ex[q] = __expf(leaky02(hs[s[q]] + hdn + p[q].y * c) - ub);
                denom += ex[q];
            }
            if (VL == 4) {
                uint2 r[8];
                #pragma unroll
                for (int q = 0; q < 8; q++)
                    r[q] = *(const uint2*)(h + (size_t)s[q] * C + loff);
                #pragma unroll
                for (int q = 0; q < 8; q++) {
                    float2 a = __half22float2(*(__half2*)&r[q].x);
                    float2 b = __half22float2(*(__half2*)&r[q].y);
                    acc[0] += ex[q] * a.x; acc[1] += ex[q] * a.y;
                    acc[2] += ex[q] * b.x; acc[3] += ex[q] * b.y;
                }
            } else {
                uint32_t r[8];
                #pragma unroll
                for (int q = 0; q < 8; q++)
                    r[q] = *(const uint32_t*)(h + (size_t)s[q] * C + loff);
                #pragma unroll
                for (int q = 0; q < 8; q++) {
                    float2 a = __half22float2(*(__half2*)&r[q]);
                    acc[0] += ex[q] * a.x; acc[1] += ex[q] * a.y;
                }
            }
        }
        // remainder
        for (; e < end; e++) {
            float2 p = csre[e];
            int s = __float_as_int(p.x);
            colsum += p.y;
            float ex = __expf(leaky02(hs[s] + hdn + p.y * c) - ub);
            denom += ex;
            if (VL == 4) {
                uint2 r = *(const uint2*)(h + (size_t)s * C + loff);
                float2 a = __half22float2(*(__half2*)&r.x);
                float2 b = __half22float2(*(__half2*)&r.y);
                acc[0] += ex * a.x; acc[1] += ex * a.y;
                acc[2] += ex * b.x; acc[3] += ex * b.y;
            } else {
                uint32_t r = *(const uint32_t*)(h + (size_t)s * C + loff);
                float2 a = __half22float2(*(__half2*)&r);
                acc[0] += ex * a.x; acc[1] += ex * a.y;
            }
        }
        {   // self loop: loop_attr = colsum / max(deg,1)
            int deg = end - beg;
            float lattr = colsum / (float)(deg > 1 ? deg : 1);
            float aself = leaky02(hs[w] + hdn + lattr * c);
            float ex = __expf(aself - ub);
            denom += ex;
            if (VL == 4) {
                uint2 r = *(const uint2*)(h + (size_t)w * C + loff);
                float2 a = __half22float2(*(__half2*)&r.x);
                float2 b = __half22float2(*(__half2*)&r.y);
                acc[0] += ex * a.x; acc[1] += ex * a.y;
                acc[2] += ex * b.x; acc[3] += ex * b.y;
            } else {
                uint32_t r = *(const uint32_t*)(h + (size_t)w * C + loff);
                float2 a = __half22float2(*(__half2*)&r);
                acc[0] += ex * a.x; acc[1] += ex * a.y;
            }
        }
        float inv = 1.f / denom;
        #pragma unroll
        for (int j = 0; j < VL; j++) {
            float v = acc[j] * inv + bias[loff + j];
            out[j] = v > 0.f ? v : expm1f(v);
        }
        if (!POOL) {
            float* xr = xout + (size_t)w * C + loff;
            if (VL == 4) *(float4*)xr = make_float4(out[0], out[1], out[2], out[3]);
            else         *(float2*)xr = make_float2(out[0], out[1]);
        }
    }
    if (POOL) {
        if (active) {
            #pragma unroll
            for (int j = 0; j < VL; j++)
                atomicAdd(&sums[lane * VL + j], out[j]);
        }
        __syncthreads();
        if (threadIdx.x < 64) atomicAdd(&gsum[threadIdx.x], sums[threadIdx.x]);
    }
}

__global__ void head_k(const float* __restrict__ g, const float* __restrict__ xn1,
                       const float* __restrict__ xn2, const float* __restrict__ Wlin,
                       const float* __restrict__ blin, const float* __restrict__ Wc1,
                       const float* __restrict__ bc1, const float* __restrict__ Wc2,
                       const float* __restrict__ bc2, float* __restrict__ out, int n) {
    __shared__ float v[128];
    __shared__ float hh[16];
    int t = threadIdx.x;
    int gi = t >> 6, c = t & 63;
    const float* gg = g + gi * 64;
    const float* xn = gi ? xn2 : xn1;
    float inv = 1.f / (float)n;
    float s = blin[c];
    for (int k = 0; k < 64; k++) s += (gg[k] * inv) * Wlin[k * 64 + c];
    for (int k = 0; k < 16; k++) s += xn[k] * Wlin[(64 + k) * 64 + c];
    v[t] = s;
    __syncthreads();
    if (t < 16) {
        float a = bc1[t];
        for (int k = 0; k < 128; k++) a += v[k] * Wc1[k * 16 + t];
        hh[t] = fmaxf(a, 0.f);
    }
    __syncthreads();
    if (t < 3) {
        float a = bc2[t];
        for (int k = 0; k < 16; k++) a += hh[k] * Wc2[k * 3 + t];
        out[t] = a;
    }
}

// ---------------------------------------------------------------------------
extern "C" void kernel_launch(void* const* d_in, const int* in_sizes, int n_in,
                              void* d_out, int out_size) {
    const int IN = 7;
    const int N = in_sizes[0] / IN;
    const int E = in_sizes[2] / 2;

    static cudaStream_t s1 = nullptr, sCsr = nullptr;
    static cudaEvent_t evF = nullptr, evP = nullptr, evC = nullptr, evJ = nullptr;
    if (!s1) {
        cudaStreamCreateWithFlags(&s1, cudaStreamNonBlocking);
        cudaStreamCreateWithFlags(&sCsr, cudaStreamNonBlocking);
        cudaEventCreateWithFlags(&evF, cudaEventDisableTiming);
        cudaEventCreateWithFlags(&evP, cudaEventDisableTiming);
        cudaEventCreateWithFlags(&evC, cudaEventDisableTiming);
        cudaEventCreateWithFlags(&evJ, cudaEventDisableTiming);
        cudaFuncSetAttribute(gemm_mma_k<128>,
                             cudaFuncAttributeMaxDynamicSharedMemorySize, 71680);
        cudaFuncSetAttribute(gemm_mma_k<64>,
                             cudaFuncAttributeMaxDynamicSharedMemorySize, 55296);
    }

    float *b_x, *b_hs, *b_hd, *p_g, *b_c;
    float2* b_csre;
    __half* b_hh;
    unsigned* b_max;
    int *b_deg, *b_offs, *b_cursor, *b_tsum;
    __nv_bfloat16 *b_wbh, *b_wbl;
    cudaGetSymbolAddress((void**)&b_hh, g_hh);
    cudaGetSymbolAddress((void**)&b_x, g_x);
    cudaGetSymbolAddress((void**)&b_hs, g_hs);
    cudaGetSymbolAddress((void**)&b_hd, g_hd);
    cudaGetSymbolAddress((void**)&b_csre, g_csre);
    cudaGetSymbolAddress((void**)&p_g, g_gvec);
    cudaGetSymbolAddress((void**)&b_c, g_c);
    cudaGetSymbolAddress((void**)&b_max, g_maxhs);
    cudaGetSymbolAddress((void**)&b_deg, g_deg);
    cudaGetSymbolAddress((void**)&b_offs, g_offs);
    cudaGetSymbolAddress((void**)&b_cursor, g_cursor);
    cudaGetSymbolAddress((void**)&b_tsum, g_tsum);
    cudaGetSymbolAddress((void**)&b_wbh, g_wbh);
    cudaGetSymbolAddress((void**)&b_wbl, g_wbl);

    const float* x_in[2]  = {(const float*)d_in[0], (const float*)d_in[1]};
    const int*   ei[2]    = {(const int*)d_in[2], (const int*)d_in[3]};
    const float* xnorm[2] = {(const float*)d_in[4], (const float*)d_in[5]};
    const float* ecol[2]  = {(const float*)d_in[6], (const float*)d_in[7]};

    const float* W[3]; const float* asrc[3]; const float* adst[3];
    const float* We[3]; const float* ae[3]; const float* bb[3];
    for (int l = 0; l < 3; l++) {
        W[l]    = (const float*)d_in[8 + 6 * l + 0];
        asrc[l] = (const float*)d_in[8 + 6 * l + 1];
        adst[l] = (const float*)d_in[8 + 6 * l + 2];
        We[l]   = (const float*)d_in[8 + 6 * l + 3];
        ae[l]   = (const float*)d_in[8 + 6 * l + 4];
        bb[l]   = (const float*)d_in[8 + 6 * l + 5];
    }
    const float* Wlin = (const float*)d_in[26];
    const float* blin = (const float*)d_in[27];
    const float* Wc1  = (const float*)d_in[28];
    const float* bc1  = (const float*)d_in[29];
    const float* Wc2  = (const float*)d_in[30];
    const float* bc2  = (const float*)d_in[31];

    const int eHalfBlocks = (E + 255) / 256;
    const int nT = (N + TILE - 1) / TILE;
    const int tcBlocks = (N + 127) / 128;
    const int g7Blocks = (N + 7) / 8;
    const int aggBlocks = (N * 32 + 255) / 256;

    // fork point: all side streams branch from stream 0 (capture-legal)
    cudaEventRecord(evF, 0);
    cudaStreamWaitEvent(sCsr, evF, 0);
    cudaStreamWaitEvent(s1, evF, 0);

    // batched CSR build on side stream
    cudaMemsetAsync(b_deg, 0, 2 * MAX_N * sizeof(int), sCsr);
    build_deg_k<<<eHalfBlocks, 256, 0, sCsr>>>(ei[0], ei[1], b_deg, E);
    scan1_k<<<2 * nT, 256, 0, sCsr>>>(b_deg, b_tsum, N, nT);
    scan2_k<<<1, 256, 0, sCsr>>>(b_tsum, nT);
    scan3_k<<<2 * nT, TILE, 0, sCsr>>>(b_deg, b_tsum, b_offs, b_cursor, N, nT);
    scatter_k<<<eHalfBlocks, 256, 0, sCsr>>>(ei[0], ecol[0], ei[1], ecol[1],
                                             b_cursor, b_csre, E);
    cudaEventRecord(evC, sCsr);

    // prologue on stream 0 (graph-invariant), concurrent with CSR
    cudaMemsetAsync(p_g, 0, 128 * sizeof(float), 0);
    cudaMemsetAsync(b_max, 0, 6 * sizeof(unsigned), 0);
    wsplit_k<<<(128 * 128 + 255) / 256, 256, 0, 0>>>(W[1], b_wbh, b_wbl, 128 * 128);
    wsplit_k<<<(128 * 64 + 255) / 256, 256, 0, 0>>>(W[2], b_wbh + 128 * 128,
                                                    b_wbl + 128 * 128, 128 * 64);
    cscalar3_k<<<1, 96, 0, 0>>>(We[0], ae[0], We[1], ae[1], We[2], ae[2], b_c);
    cudaEventRecord(evP, 0);
    cudaStreamWaitEvent(s1, evP, 0);

    // per-graph chains on two streams
    for (int gph = 0; gph < 2; gph++) {
        cudaStream_t st = gph ? s1 : (cudaStream_t)0;
        __half* p_hh = b_hh + (size_t)gph * MAX_N * 128;
        float* p_x = b_x + (size_t)gph * MAX_N * 128;
        float* p_hs = b_hs + gph * MAX_N;
        float* p_hd = b_hd + gph * MAX_N;
        float2* p_csre = b_csre + (size_t)gph * MAX_E;
        int* p_offs = b_offs + gph * (MAX_N + 1);

        gemm7_k<<<g7Blocks, 256, 0, st>>>(x_in[gph], W[0], asrc[0], adst[0],
                                          p_hh, p_hs, p_hd, b_max + 0 + gph, N);
        cudaStreamWaitEvent(st, evC, 0);

        gat_agg_k<128, false><<<aggBlocks, 256, 0, st>>>(
            p_hh, p_hs, p_hd, p_offs, p_csre, bb[0], b_c + 0,
            b_max + 0 + gph, p_x, nullptr, N);
        gemm_mma_k<128><<<tcBlocks, 256, 71680, st>>>(
            p_x, b_wbh, b_wbl, asrc[1], adst[1], p_hh, p_hs, p_hd,
            b_max + 2 + gph, N);
        gat_agg_k<128, false><<<aggBlocks, 256, 0, st>>>(
            p_hh, p_hs, p_hd, p_offs, p_csre, bb[1], b_c + 1,
            b_max + 2 + gph, p_x, nullptr, N);
        gemm_mma_k<64><<<tcBlocks, 256, 55296, st>>>(
            p_x, b_wbh + 128 * 128, b_wbl + 128 * 128, asrc[2], adst[2],
            p_hh, p_hs, p_hd, b_max + 4 + gph, N);
        // layer-2 aggregation with fused mean-pool (no x write, no colsum)
        gat_agg_k<64, true><<<aggBlocks, 256, 0, st>>>(
            p_hh, p_hs, p_hd, p_offs, p_csre, bb[2], b_c + 2,
            b_max + 4 + gph, nullptr, p_g + gph * 64, N);
    }

    cudaEventRecord(evJ, s1);
    cudaStreamWaitEvent((cudaStream_t)0, evJ, 0);
    head_k<<<1, 128, 0, 0>>>(p_g, xnorm[0], xnorm[1], Wlin, blin, Wc1, bc1, Wc2, bc2,
                             (float*)d_out, N);
}

// round 14
// speedup vs baseline: 1.1301x; 1.0597x over previous
#include <cuda_runtime.h>
#include <cuda_bf16.h>
#include <cuda_fp16.h>
#include <math.h>
#include <stdint.h>

// ---------------------------------------------------------------------------
// SpatialModel: 3-layer GATConv on two graphs (N=50000, E=800000), mean pool,
// MLP head -> [1,3] logits.
//
// R14: inter-layer x stored fp16 (agg writes half, gemm_mma splits fp16 ->
// bf16 hi/lo losslessly), x4 mid-tier in agg remainder. Otherwise R13:
// x8-unrolled single-pass agg with fused mean-pool on layer 2, two-stream
// per-graph pipeline, batched CSR side stream, K-chunked bf16-split mma.
// ---------------------------------------------------------------------------

#define MAX_N 50000
#define MAX_E 800000
#define TILE 512

__device__ __align__(16) __half g_hh[2][MAX_N * 128];
__device__ __align__(16) __half g_xh[2][MAX_N * 128];
__device__ float g_hs[2][MAX_N];
__device__ float g_hd[2][MAX_N];
__device__ int   g_deg[2][MAX_N];
__device__ int   g_offs[2][MAX_N + 1];
__device__ int   g_cursor[2][MAX_N];
__device__ __align__(16) float2 g_csre[2][MAX_E];
__device__ int   g_tsum[2][128];
__device__ float g_c[3];
__device__ unsigned g_maxhs[6];     // [layer*2 + graph]
__device__ float g_gvec[128];
__device__ __align__(16) __nv_bfloat16 g_wbh[2][128 * 128];
__device__ __align__(16) __nv_bfloat16 g_wbl[2][128 * 128];

// ---------------------------------------------------------------------------
__device__ __forceinline__ uint32_t smem_u32(const void* p) {
    uint32_t a;
    asm("{ .reg .u64 t; cvta.to.shared.u64 t, %1; cvt.u32.u64 %0, t; }"
        : "=r"(a) : "l"(p));
    return a;
}
__device__ __forceinline__ unsigned fkey(float f) {
    int i = __float_as_int(f);
    return i >= 0 ? ((unsigned)i | 0x80000000u) : ~(unsigned)i;
}
__device__ __forceinline__ float funkey(unsigned k) {
    return (k & 0x80000000u) ? __int_as_float((int)(k & 0x7FFFFFFFu))
                             : __int_as_float((int)~k);
}
#define LDSM_X4(r0, r1, r2, r3, addr)                                          \
    asm volatile("ldmatrix.sync.aligned.m8n8.x4.shared.b16 {%0,%1,%2,%3}, [%4];" \
                 : "=r"(r0), "=r"(r1), "=r"(r2), "=r"(r3) : "r"(addr))
#define LDSM_X4_T(r0, r1, r2, r3, addr)                                        \
    asm volatile("ldmatrix.sync.aligned.m8n8.x4.trans.shared.b16 {%0,%1,%2,%3}, [%4];" \
                 : "=r"(r0), "=r"(r1), "=r"(r2), "=r"(r3) : "r"(addr))
__device__ __forceinline__ void mma16816(float* c, uint32_t a0, uint32_t a1,
                                         uint32_t a2, uint32_t a3,
                                         uint32_t b0, uint32_t b1) {
    asm volatile(
        "mma.sync.aligned.m16n8k16.row.col.f32.bf16.bf16.f32 "
        "{%0,%1,%2,%3}, {%4,%5,%6,%7}, {%8,%9}, {%0,%1,%2,%3};"
        : "+f"(c[0]), "+f"(c[1]), "+f"(c[2]), "+f"(c[3])
        : "r"(a0), "r"(a1), "r"(a2), "r"(a3), "r"(b0), "r"(b1));
}

// ---------------------------------------------------------------------------
__global__ void build_deg_k(const int* __restrict__ ei0, const int* __restrict__ ei1,
                            int* deg, int E) {
    int i = (blockIdx.x * blockDim.x + threadIdx.x) * 2;
    if (i >= 2 * E) return;
    int g = (i >= E);
    int j = i - g * E;
    const int* dst = (g ? ei1 : ei0) + E;
    int d0 = dst[j];
    int d1 = dst[j + 1];
    atomicAdd(&deg[g * MAX_N + d0], 1);
    atomicAdd(&deg[g * MAX_N + d1], 1);
}

__global__ void scan1_k(const int* __restrict__ deg, int* tsum, int n, int nT) {
    __shared__ int sh[256];
    int bx = blockIdx.x, t = threadIdx.x;
    int g = (bx >= nT);
    int b = bx - g * nT;
    const int* dg = deg + g * MAX_N;
    int i0 = b * TILE;
    int s = 0;
    int i = i0 + t;        if (i < n) s += dg[i];
    i = i0 + 256 + t;      if (i < n) s += dg[i];
    sh[t] = s;
    __syncthreads();
    for (int o = 128; o; o >>= 1) { if (t < o) sh[t] += sh[t + o]; __syncthreads(); }
    if (t == 0) tsum[g * 128 + b] = sh[0];
}
__global__ void scan2_k(int* tsum, int nT) {
    __shared__ int sh[256];
    int t = threadIdx.x;
    int g = t >> 7, tl = t & 127;
    int v0 = (tl < nT) ? tsum[g * 128 + tl] : 0;
    sh[t] = v0;
    __syncthreads();
    for (int d = 1; d < 128; d <<= 1) {
        int v = (tl >= d) ? sh[t - d] : 0;
        __syncthreads();
        sh[t] += v;
        __syncthreads();
    }
    if (tl < nT) tsum[g * 128 + tl] = sh[t] - v0;
}
__global__ void scan3_k(const int* __restrict__ deg, const int* __restrict__ tsum,
                        int* offs, int* cursor, int n, int nT) {
    __shared__ int sh[TILE];
    int bx = blockIdx.x, t = threadIdx.x;
    int g = (bx >= nT);
    int b = bx - g * nT;
    const int* dg = deg + g * MAX_N;
    const int* ts = tsum + g * 128;
    int* of = offs + g * (MAX_N + 1);
    int* cu = cursor + g * MAX_N;
    int i = b * TILE + t;
    int d = (i < n) ? dg[i] : 0;
    sh[t] = d;
    __syncthreads();
    for (int o = 1; o < TILE; o <<= 1) {
        int v = (t >= o) ? sh[t - o] : 0;
        __syncthreads();
        sh[t] += v;
        __syncthreads();
    }
    if (i < n) {
        int base = ts[b];
        int off = base + sh[t] - d;
        of[i] = off;
        cu[i] = off;
        if (i == n - 1) of[n] = base + sh[t];
    }
}

__global__ void scatter_k(const int* __restrict__ ei0, const float* __restrict__ col0,
                          const int* __restrict__ ei1, const float* __restrict__ col1,
                          int* cursor, float2* csre, int E) {
    int i = (blockIdx.x * blockDim.x + threadIdx.x) * 2;
    if (i >= 2 * E) return;
    int g = (i >= E);
    int j = i - g * E;
    const int* ei = g ? ei1 : ei0;
    const float* col = g ? col1 : col0;
    int* cur = cursor + g * MAX_N;
    float2* cs = csre + (size_t)g * MAX_E;
    int s0 = ei[j], s1 = ei[j + 1];
    int d0 = ei[E + j], d1 = ei[E + j + 1];
    float c0 = col[j], c1 = col[j + 1];
    int p0 = atomicAdd(&cur[d0], 1);
    int p1 = atomicAdd(&cur[d1], 1);
    cs[p0] = make_float2(__int_as_float(s0), c0);
    cs[p1] = make_float2(__int_as_float(s1), c1);
}

// ---------------------------------------------------------------------------
__global__ void wsplit_k(const float* __restrict__ W, __nv_bfloat16* hi,
                         __nv_bfloat16* lo, int n) {
    int i = blockIdx.x * blockDim.x + threadIdx.x;
    if (i >= n) return;
    float v = W[i];
    __nv_bfloat16 h = __float2bfloat16_rn(v);
    hi[i] = h;
    lo[i] = __float2bfloat16_rn(v - __bfloat162float(h));
}

__global__ void cscalar3_k(const float* __restrict__ We1, const float* __restrict__ ae1,
                           const float* __restrict__ We2, const float* __restrict__ ae2,
                           const float* __restrict__ We3, const float* __restrict__ ae3,
                           float* out) {
    int w = threadIdx.x >> 5, lane = threadIdx.x & 31;
    if (w >= 3) return;
    const float* We = (w == 0) ? We1 : (w == 1) ? We2 : We3;
    const float* ae = (w == 0) ? ae1 : (w == 1) ? ae2 : ae3;
    int C = (w == 2) ? 64 : 128;
    float s = 0.f;
    for (int k = lane; k < C; k += 32) s += We[k] * ae[k];
    #pragma unroll
    for (int o = 16; o; o >>= 1) s += __shfl_xor_sync(0xffffffffu, s, o);
    if (lane == 0) out[w] = s;
}

// ---------------------------------------------------------------------------
__global__ void __launch_bounds__(256)
gemm7_k(const float* __restrict__ x, const float* __restrict__ W,
        const float* __restrict__ asrc, const float* __restrict__ adst,
        __half* __restrict__ h, float* __restrict__ hs, float* __restrict__ hd,
        unsigned* __restrict__ gmax, int M) {
    __shared__ float Ws[7 * 128], As[128], Ad[128];
    __shared__ float wmax[8];
    int t = threadIdx.x;
    for (int i = t; i < 7 * 128; i += 256) Ws[i] = W[i];
    if (t < 128) { As[t] = asrc[t]; Ad[t] = adst[t]; }
    __syncthreads();
    int r = blockIdx.x * 8 + (t >> 5);
    bool active = (r < M);
    int lane = t & 31, c0 = lane * 4;
    float s = 0.f, d = 0.f;
    if (active) {
        float xv[7];
        #pragma unroll
        for (int k = 0; k < 7; k++) xv[k] = x[(size_t)r * 7 + k];
        float out[4];
        #pragma unroll
        for (int j = 0; j < 4; j++) {
            float acc = 0.f;
            #pragma unroll
            for (int k = 0; k < 7; k++) acc += xv[k] * Ws[k * 128 + c0 + j];
            out[j] = acc;
        }
        __half2 p0 = __floats2half2_rn(out[0], out[1]);
        __half2 p1 = __floats2half2_rn(out[2], out[3]);
        uint2 u = make_uint2(*(uint32_t*)&p0, *(uint32_t*)&p1);
        *(uint2*)(h + (size_t)r * 128 + c0) = u;
        s = out[0] * As[c0] + out[1] * As[c0 + 1] + out[2] * As[c0 + 2] + out[3] * As[c0 + 3];
        d = out[0] * Ad[c0] + out[1] * Ad[c0 + 1] + out[2] * Ad[c0 + 2] + out[3] * Ad[c0 + 3];
        #pragma unroll
        for (int o = 16; o; o >>= 1) {
            s += __shfl_xor_sync(0xffffffffu, s, o);
            d += __shfl_xor_sync(0xffffffffu, d, o);
        }
        if (lane == 0) { hs[r] = s; hd[r] = d; }
    }
    if (lane == 0) wmax[t >> 5] = active ? s : -3.4e38f;
    __syncthreads();
    if (t == 0) {
        float m = wmax[0];
        #pragma unroll
        for (int i = 1; i < 8; i++) m = fmaxf(m, wmax[i]);
        atomicMax(gmax, fkey(m));
    }
}

// ---------------------------------------------------------------------------
// A input now fp16 (from agg). fp16 -> bf16 hi/lo split is lossless.
template <int CN>
__global__ void __launch_bounds__(256, 2)
gemm_mma_k(const __half* __restrict__ A, const __nv_bfloat16* __restrict__ Bh,
           const __nv_bfloat16* __restrict__ Bl,
           const float* __restrict__ asrc, const float* __restrict__ adst,
           __half* __restrict__ H, float* __restrict__ hs, float* __restrict__ hd,
           unsigned* __restrict__ gmax, int M) {
    extern __shared__ char smem[];
    constexpr int SA = 72;
    constexpr int SB = CN + 8;
    constexpr int AH = 0;
    constexpr int AL = 128 * SA * 2;
    constexpr int BH = 2 * AL;
    constexpr int BL = BH + 64 * SB * 2;
    constexpr int NT = CN / 16;
    constexpr int NC8 = CN / 8;

    int tid = threadIdx.x, lane = tid & 31, warp = tid >> 5;
    const int rowBase = blockIdx.x * 128;

    __nv_bfloat16* as_h = (__nv_bfloat16*)(smem + AH);
    __nv_bfloat16* as_l = (__nv_bfloat16*)(smem + AL);
    __nv_bfloat16* bs_h = (__nv_bfloat16*)(smem + BH);
    __nv_bfloat16* bs_l = (__nv_bfloat16*)(smem + BL);

    int wm = warp >> 1, wn = warp & 1;
    int m0 = wm * 32, n0 = wn * (CN / 2);

    float acc[2][NT][4];
    #pragma unroll
    for (int a = 0; a < 2; a++)
        #pragma unroll
        for (int b = 0; b < NT; b++)
            #pragma unroll
            for (int q = 0; q < 4; q++) acc[a][b][q] = 0.f;

    int lr = lane & 15, lc = lane >> 4;
    uint32_t sb_ah = smem_u32(as_h), sb_al = smem_u32(as_l);
    uint32_t sb_bh = smem_u32(bs_h), sb_bl = smem_u32(bs_l);

    #pragma unroll
    for (int kc = 0; kc < 128; kc += 64) {
        // load + split A chunk (128 rows x 64 halfs): uint4 = 8 halfs/thread-iter
        #pragma unroll
        for (int q = 0; q < 4; q++) {
            int i = q * 256 + tid;          // 1024 uint4 total
            int r = i >> 3, c8 = i & 7;
            int gr = rowBase + r;
            uint4 u = make_uint4(0u, 0u, 0u, 0u);
            if (gr < M) u = *(const uint4*)(A + (size_t)gr * 128 + kc + c8 * 8);
            const __half2* hp = (const __half2*)&u;
            int base = r * SA + c8 * 8;
            #pragma unroll
            for (int j = 0; j < 4; j++) {
                float2 v = __half22float2(hp[j]);
                __nv_bfloat16 h0 = __float2bfloat16_rn(v.x);
                __nv_bfloat16 h1 = __float2bfloat16_rn(v.y);
                float l0 = v.x - __bfloat162float(h0);
                float l1 = v.y - __bfloat162float(h1);
                *(__nv_bfloat162*)(as_h + base + j * 2) = __nv_bfloat162(h0, h1);
                *(__nv_bfloat162*)(as_l + base + j * 2) =
                    __nv_bfloat162(__float2bfloat16_rn(l0), __float2bfloat16_rn(l1));
            }
        }
        for (int i = tid; i < 64 * NC8; i += 256) {
            int r = i / NC8, c8 = i % NC8;
            int gi = (kc + r) * NC8 + c8;
            *(uint4*)(bs_h + r * SB + c8 * 8) = ((const uint4*)Bh)[gi];
            *(uint4*)(bs_l + r * SB + c8 * 8) = ((const uint4*)Bl)[gi];
        }
        __syncthreads();

        #pragma unroll
        for (int ks = 0; ks < 4; ks++) {
            int k0 = ks * 16;
            uint32_t ah[2][4], al[2][4];
            #pragma unroll
            for (int mt = 0; mt < 2; mt++) {
                uint32_t off = ((m0 + mt * 16 + lr) * SA + k0 + lc * 8) * 2;
                LDSM_X4(ah[mt][0], ah[mt][1], ah[mt][2], ah[mt][3], sb_ah + off);
                LDSM_X4(al[mt][0], al[mt][1], al[mt][2], al[mt][3], sb_al + off);
            }
            #pragma unroll
            for (int n16 = 0; n16 < NT / 2; n16++) {
                uint32_t off = ((k0 + lr) * SB + n0 + n16 * 16 + lc * 8) * 2;
                uint32_t b0h, b1h, b2h, b3h, b0l, b1l, b2l, b3l;
                LDSM_X4_T(b0h, b1h, b2h, b3h, sb_bh + off);
                LDSM_X4_T(b0l, b1l, b2l, b3l, sb_bl + off);
                int nt0 = 2 * n16, nt1 = 2 * n16 + 1;
                #pragma unroll
                for (int mt = 0; mt < 2; mt++) {
                    mma16816(acc[mt][nt0], ah[mt][0], ah[mt][1], ah[mt][2], ah[mt][3], b0h, b1h);
                    mma16816(acc[mt][nt0], ah[mt][0], ah[mt][1], ah[mt][2], ah[mt][3], b0l, b1l);
                    mma16816(acc[mt][nt0], al[mt][0], al[mt][1], al[mt][2], al[mt][3], b0h, b1h);
                    mma16816(acc[mt][nt1], ah[mt][0], ah[mt][1], ah[mt][2], ah[mt][3], b2h, b3h);
                    mma16816(acc[mt][nt1], ah[mt][0], ah[mt][1], ah[mt][2], ah[mt][3], b2l, b3l);
                    mma16816(acc[mt][nt1], al[mt][0], al[mt][1], al[mt][2], al[mt][3], b2h, b3h);
                }
            }
        }
        __syncthreads();
    }

    int g = lane >> 2, tig = lane & 3;
    #pragma unroll
    for (int mt = 0; mt < 2; mt++) {
        int r0 = rowBase + m0 + mt * 16 + g;
        int r1 = r0 + 8;
        #pragma unroll
        for (int nt = 0; nt < NT; nt++) {
            int col = n0 + nt * 8 + tig * 2;
            if (r0 < M)
                *(__half2*)(H + (size_t)r0 * CN + col) =
                    __floats2half2_rn(acc[mt][nt][0], acc[mt][nt][1]);
            if (r1 < M)
                *(__half2*)(H + (size_t)r1 * CN + col) =
                    __floats2half2_rn(acc[mt][nt][2], acc[mt][nt][3]);
        }
    }

    float sd[2][2] = {}, dd[2][2] = {};
    #pragma unroll
    for (int mt = 0; mt < 2; mt++)
        #pragma unroll
        for (int nt = 0; nt < NT; nt++) {
            int col = n0 + nt * 8 + tig * 2;
            float a0 = __ldg(asrc + col), a1 = __ldg(asrc + col + 1);
            float d0 = __ldg(adst + col), d1 = __ldg(adst + col + 1);
            sd[mt][0] += acc[mt][nt][0] * a0 + acc[mt][nt][1] * a1;
            dd[mt][0] += acc[mt][nt][0] * d0 + acc[mt][nt][1] * d1;
            sd[mt][1] += acc[mt][nt][2] * a0 + acc[mt][nt][3] * a1;
            dd[mt][1] += acc[mt][nt][2] * d0 + acc[mt][nt][3] * d1;
        }
    #pragma unroll
    for (int o = 1; o < 4; o <<= 1) {
        #pragma unroll
        for (int mt = 0; mt < 2; mt++)
            #pragma unroll
            for (int j = 0; j < 2; j++) {
                sd[mt][j] += __shfl_xor_sync(0xffffffffu, sd[mt][j], o);
                dd[mt][j] += __shfl_xor_sync(0xffffffffu, dd[mt][j], o);
            }
    }
    __syncthreads();
    float* red = (float*)smem;
    if (wn == 1 && tig == 0) {
        #pragma unroll
        for (int mt = 0; mt < 2; mt++)
            #pragma unroll
            for (int j = 0; j < 2; j++) {
                int lrow = m0 + mt * 16 + g + j * 8;
                red[lrow] = sd[mt][j];
                red[128 + lrow] = dd[mt][j];
            }
    }
    __syncthreads();
    float hsmax = -3.4e38f;
    if (wn == 0 && tig == 0) {
        #pragma unroll
        for (int mt = 0; mt < 2; mt++)
            #pragma unroll
            for (int j = 0; j < 2; j++) {
                int lrow = m0 + mt * 16 + g + j * 8;
                int gr = rowBase + lrow;
                if (gr < M) {
                    float sv = sd[mt][j] + red[lrow];
                    hs[gr] = sv;
                    hd[gr] = dd[mt][j] + red[128 + lrow];
                    hsmax = fmaxf(hsmax, sv);
                }
            }
    }
    #pragma unroll
    for (int o = 16; o; o >>= 1)
        hsmax = fmaxf(hsmax, __shfl_xor_sync(0xffffffffu, hsmax, o));
    if (wn == 0 && lane == 0) atomicMax(gmax, fkey(hsmax));
}

// ---------------------------------------------------------------------------
__device__ __forceinline__ float leaky02(float a) {
    return a > 0.f ? a : 0.2f * a;
}

// warp-per-node single-pass GAT agg; x8 + x4 + scalar tiers; fp16 x output.
// POOL: skip x write, accumulate block-level mean-pool partials into gsum.
template <int C, bool POOL>
__global__ void __launch_bounds__(256)
gat_agg_k(const __half* __restrict__ h, const float* __restrict__ hs,
          const float* __restrict__ hd, const int* __restrict__ offs,
          const float2* __restrict__ csre,
          const float* __restrict__ bias,
          const float* __restrict__ cptr, const unsigned* __restrict__ gmax,
          __half* __restrict__ xout, float* __restrict__ gsum, int n) {
    constexpr int VL = C / 32;
    __shared__ float sums[64];
    int w = (blockIdx.x * blockDim.x + threadIdx.x) >> 5;
    int lane = threadIdx.x & 31;
    bool active = (w < n);

    if (POOL) {
        if (threadIdx.x < 64) sums[threadIdx.x] = 0.f;
        __syncthreads();
    }

    float out[VL];
    if (active) {
        float c = *cptr;
        float hdn = hd[w];
        float ub = leaky02(funkey(*gmax) + hdn + fmaxf(c, 0.f));
        int beg = offs[w], end = offs[w + 1];

        float acc[VL];
        #pragma unroll
        for (int j = 0; j < VL; j++) acc[j] = 0.f;
        float denom = 0.f;
        float colsum = 0.f;
        const size_t loff = (size_t)lane * VL;

        int e = beg;
        for (; e + 8 <= end; e += 8) {
            float2 p[8]; int s[8]; float ex[8];
            #pragma unroll
            for (int q = 0; q < 8; q++) p[q] = csre[e + q];
            #pragma unroll
            for (int q = 0; q < 8; q++) {
                s[q] = __float_as_int(p[q].x);
                colsum += p[q].y;
            }
            #pragma unroll
            for (int q = 0; q < 8; q++) {
                ex[q] = __expf(leaky02(hs[s[q]] + hdn + p[q].y * c) - ub);
                denom += ex[q];
            }
            if (VL == 4) {
                uint2 r[8];
                #pragma unroll
                for (int q = 0; q < 8; q++)
                    r[q] = *(const uint2*)(h + (size_t)s[q] * C + loff);
                #pragma unroll
                for (int q = 0; q < 8; q++) {
                    float2 a = __half22float2(*(__half2*)&r[q].x);
                    float2 b = __half22float2(*(__half2*)&r[q].y);
                    acc[0] += ex[q] * a.x; acc[1] += ex[q] * a.y;
                    acc[2] += ex[q] * b.x; acc[3] += ex[q] * b.y;
                }
            } else {
                uint32_t r[8];
                #pragma unroll
                for (int q = 0; q < 8; q++)
                    r[q] = *(const uint32_t*)(h + (size_t)s[q] * C + loff);
                #pragma unroll
                for (int q = 0; q < 8; q++) {
                    float2 a = __half22float2(*(__half2*)&r[q]);
                    acc[0] += ex[q] * a.x; acc[1] += ex[q] * a.y;
                }
            }
        }
        // x4 mid tier
        for (; e + 4 <= end; e += 4) {
            float2 p[4]; int s[4]; float ex[4];
            #pragma unroll
            for (int q = 0; q < 4; q++) p[q] = csre[e + q];
            #pragma unroll
            for (int q = 0; q < 4; q++) {
                s[q] = __float_as_int(p[q].x);
                colsum += p[q].y;
            }
            #pragma unroll
            for (int q = 0; q < 4; q++) {
                ex[q] = __expf(leaky02(hs[s[q]] + hdn + p[q].y * c) - ub);
                denom += ex[q];
            }
            if (VL == 4) {
                uint2 r[4];
                #pragma unroll
                for (int q = 0; q < 4; q++)
                    r[q] = *(const uint2*)(h + (size_t)s[q] * C + loff);
                #pragma unroll
                for (int q = 0; q < 4; q++) {
                    float2 a = __half22float2(*(__half2*)&r[q].x);
                    float2 b = __half22float2(*(__half2*)&r[q].y);
                    acc[0] += ex[q] * a.x; acc[1] += ex[q] * a.y;
                    acc[2] += ex[q] * b.x; acc[3] += ex[q] * b.y;
                }
            } else {
                uint32_t r[4];
                #pragma unroll
                for (int q = 0; q < 4; q++)
                    r[q] = *(const uint32_t*)(h + (size_t)s[q] * C + loff);
                #pragma unroll
                for (int q = 0; q < 4; q++) {
                    float2 a = __half22float2(*(__half2*)&r[q]);
                    acc[0] += ex[q] * a.x; acc[1] += ex[q] * a.y;
                }
            }
        }
        for (; e < end; e++) {
            float2 p = csre[e];
            int s = __float_as_int(p.x);
            colsum += p.y;
            float ex = __expf(leaky02(hs[s] + hdn + p.y * c) - ub);
            denom += ex;
            if (VL == 4) {
                uint2 r = *(const uint2*)(h + (size_t)s * C + loff);
                float2 a = __half22float2(*(__half2*)&r.x);
                float2 b = __half22float2(*(__half2*)&r.y);
                acc[0] += ex * a.x; acc[1] += ex * a.y;
                acc[2] += ex * b.x; acc[3] += ex * b.y;
            } else {
                uint32_t r = *(const uint32_t*)(h + (size_t)s * C + loff);
                float2 a = __half22float2(*(__half2*)&r);
                acc[0] += ex * a.x; acc[1] += ex * a.y;
            }
        }
        {   // self loop
            int deg = end - beg;
            float lattr = colsum / (float)(deg > 1 ? deg : 1);
            float aself = leaky02(hs[w] + hdn + lattr * c);
            float ex = __expf(aself - ub);
            denom += ex;
            if (VL == 4) {
                uint2 r = *(const uint2*)(h + (size_t)w * C + loff);
                float2 a = __half22float2(*(__half2*)&r.x);
                float2 b = __half22float2(*(__half2*)&r.y);
                acc[0] += ex * a.x; acc[1] += ex * a.y;
                acc[2] += ex * b.x; acc[3] += ex * b.y;
            } else {
                uint32_t r = *(const uint32_t*)(h + (size_t)w * C + loff);
                float2 a = __half22float2(*(__half2*)&r);
                acc[0] += ex * a.x; acc[1] += ex * a.y;
            }
        }
        float inv = 1.f / denom;
        #pragma unroll
        for (int j = 0; j < VL; j++) {
            float v = acc[j] * inv + bias[loff + j];
            out[j] = v > 0.f ? v : expm1f(v);
        }
        if (!POOL) {
            __half* xr = xout + (size_t)w * C + loff;
            if (VL == 4) {
                __half2 q0 = __floats2half2_rn(out[0], out[1]);
                __half2 q1 = __floats2half2_rn(out[2], out[3]);
                *(uint2*)xr = make_uint2(*(uint32_t*)&q0, *(uint32_t*)&q1);
            } else {
                __half2 q0 = __floats2half2_rn(out[0], out[1]);
                *(uint32_t*)xr = *(uint32_t*)&q0;
            }
        }
    }
    if (POOL) {
        if (active) {
            #pragma unroll
            for (int j = 0; j < VL; j++)
                atomicAdd(&sums[lane * VL + j], out[j]);
        }
        __syncthreads();
        if (threadIdx.x < 64) atomicAdd(&gsum[threadIdx.x], sums[threadIdx.x]);
    }
}

__global__ void head_k(const float* __restrict__ g, const float* __restrict__ xn1,
                       const float* __restrict__ xn2, const float* __restrict__ Wlin,
                       const float* __restrict__ blin, const float* __restrict__ Wc1,
                       const float* __restrict__ bc1, const float* __restrict__ Wc2,
                       const float* __restrict__ bc2, float* __restrict__ out, int n) {
    __shared__ float v[128];
    __shared__ float hh[16];
    int t = threadIdx.x;
    int gi = t >> 6, c = t & 63;
    const float* gg = g + gi * 64;
    const float* xn = gi ? xn2 : xn1;
    float inv = 1.f / (float)n;
    float s = blin[c];
    for (int k = 0; k < 64; k++) s += (gg[k] * inv) * Wlin[k * 64 + c];
    for (int k = 0; k < 16; k++) s += xn[k] * Wlin[(64 + k) * 64 + c];
    v[t] = s;
    __syncthreads();
    if (t < 16) {
        float a = bc1[t];
        for (int k = 0; k < 128; k++) a += v[k] * Wc1[k * 16 + t];
        hh[t] = fmaxf(a, 0.f);
    }
    __syncthreads();
    if (t < 3) {
        float a = bc2[t];
        for (int k = 0; k < 16; k++) a += hh[k] * Wc2[k * 3 + t];
        out[t] = a;
    }
}

// ---------------------------------------------------------------------------
extern "C" void kernel_launch(void* const* d_in, const int* in_sizes, int n_in,
                              void* d_out, int out_size) {
    const int IN = 7;
    const int N = in_sizes[0] / IN;
    const int E = in_sizes[2] / 2;

    static cudaStream_t s1 = nullptr, sCsr = nullptr;
    static cudaEvent_t evF = nullptr, evP = nullptr, evC = nullptr, evJ = nullptr;
    if (!s1) {
        cudaStreamCreateWithFlags(&s1, cudaStreamNonBlocking);
        cudaStreamCreateWithFlags(&sCsr, cudaStreamNonBlocking);
        cudaEventCreateWithFlags(&evF, cudaEventDisableTiming);
        cudaEventCreateWithFlags(&evP, cudaEventDisableTiming);
        cudaEventCreateWithFlags(&evC, cudaEventDisableTiming);
        cudaEventCreateWithFlags(&evJ, cudaEventDisableTiming);
        cudaFuncSetAttribute(gemm_mma_k<128>,
                             cudaFuncAttributeMaxDynamicSharedMemorySize, 71680);
        cudaFuncSetAttribute(gemm_mma_k<64>,
                             cudaFuncAttributeMaxDynamicSharedMemorySize, 55296);
    }

    float *b_hs, *b_hd, *p_g, *b_c;
    float2* b_csre;
    __half *b_hh, *b_xh;
    unsigned* b_max;
    int *b_deg, *b_offs, *b_cursor, *b_tsum;
    __nv_bfloat16 *b_wbh, *b_wbl;
    cudaGetSymbolAddress((void**)&b_hh, g_hh);
    cudaGetSymbolAddress((void**)&b_xh, g_xh);
    cudaGetSymbolAddress((void**)&b_hs, g_hs);
    cudaGetSymbolAddress((void**)&b_hd, g_hd);
    cudaGetSymbolAddress((void**)&b_csre, g_csre);
    cudaGetSymbolAddress((void**)&p_g, g_gvec);
    cudaGetSymbolAddress((void**)&b_c, g_c);
    cudaGetSymbolAddress((void**)&b_max, g_maxhs);
    cudaGetSymbolAddress((void**)&b_deg, g_deg);
    cudaGetSymbolAddress((void**)&b_offs, g_offs);
    cudaGetSymbolAddress((void**)&b_cursor, g_cursor);
    cudaGetSymbolAddress((void**)&b_tsum, g_tsum);
    cudaGetSymbolAddress((void**)&b_wbh, g_wbh);
    cudaGetSymbolAddress((void**)&b_wbl, g_wbl);

    const float* x_in[2]  = {(const float*)d_in[0], (const float*)d_in[1]};
    const int*   ei[2]    = {(const int*)d_in[2], (const int*)d_in[3]};
    const float* xnorm[2] = {(const float*)d_in[4], (const float*)d_in[5]};
    const float* ecol[2]  = {(const float*)d_in[6], (const float*)d_in[7]};

    const float* W[3]; const float* asrc[3]; const float* adst[3];
    const float* We[3]; const float* ae[3]; const float* bb[3];
    for (int l = 0; l < 3; l++) {
        W[l]    = (const float*)d_in[8 + 6 * l + 0];
        asrc[l] = (const float*)d_in[8 + 6 * l + 1];
        adst[l] = (const float*)d_in[8 + 6 * l + 2];
        We[l]   = (const float*)d_in[8 + 6 * l + 3];
        ae[l]   = (const float*)d_in[8 + 6 * l + 4];
        bb[l]   = (const float*)d_in[8 + 6 * l + 5];
    }
    const float* Wlin = (const float*)d_in[26];
    const float* blin = (const float*)d_in[27];
    const float* Wc1  = (const float*)d_in[28];
    const float* bc1  = (const float*)d_in[29];
    const float* Wc2  = (const float*)d_in[30];
    const float* bc2  = (const float*)d_in[31];

    const int eHalfBlocks = (E + 255) / 256;
    const int nT = (N + TILE - 1) / TILE;
    const int tcBlocks = (N + 127) / 128;
    const int g7Blocks = (N + 7) / 8;
    const int aggBlocks = (N * 32 + 255) / 256;

    // fork point
    cudaEventRecord(evF, 0);
    cudaStreamWaitEvent(sCsr, evF, 0);
    cudaStreamWaitEvent(s1, evF, 0);

    // batched CSR build on side stream
    cudaMemsetAsync(b_deg, 0, 2 * MAX_N * sizeof(int), sCsr);
    build_deg_k<<<eHalfBlocks, 256, 0, sCsr>>>(ei[0], ei[1], b_deg, E);
    scan1_k<<<2 * nT, 256, 0, sCsr>>>(b_deg, b_tsum, N, nT);
    scan2_k<<<1, 256, 0, sCsr>>>(b_tsum, nT);
    scan3_k<<<2 * nT, TILE, 0, sCsr>>>(b_deg, b_tsum, b_offs, b_cursor, N, nT);
    scatter_k<<<eHalfBlocks, 256, 0, sCsr>>>(ei[0], ecol[0], ei[1], ecol[1],
                                             b_cursor, b_csre, E);
    cudaEventRecord(evC, sCsr);

    // prologue on stream 0 (graph-invariant)
    cudaMemsetAsync(p_g, 0, 128 * sizeof(float), 0);
    cudaMemsetAsync(b_max, 0, 6 * sizeof(unsigned), 0);
    wsplit_k<<<(128 * 128 + 255) / 256, 256, 0, 0>>>(W[1], b_wbh, b_wbl, 128 * 128);
    wsplit_k<<<(128 * 64 + 255) / 256, 256, 0, 0>>>(W[2], b_wbh + 128 * 128,
                                                    b_wbl + 128 * 128, 128 * 64);
    cscalar3_k<<<1, 96, 0, 0>>>(We[0], ae[0], We[1], ae[1], We[2], ae[2], b_c);
    cudaEventRecord(evP, 0);
    cudaStreamWaitEvent(s1, evP, 0);

    // per-graph chains on two streams
    for (int gph = 0; gph < 2; gph++) {
        cudaStream_t st = gph ? s1 : (cudaStream_t)0;
        __half* p_hh = b_hh + (size_t)gph * MAX_N * 128;
        __half* p_xh = b_xh + (size_t)gph * MAX_N * 128;
        float* p_hs = b_hs + gph * MAX_N;
        float* p_hd = b_hd + gph * MAX_N;
        float2* p_csre = b_csre + (size_t)gph * MAX_E;
        int* p_offs = b_offs + gph * (MAX_N + 1);

        gemm7_k<<<g7Blocks, 256, 0, st>>>(x_in[gph], W[0], asrc[0], adst[0],
                                          p_hh, p_hs, p_hd, b_max + 0 + gph, N);
        cudaStreamWaitEvent(st, evC, 0);

        gat_agg_k<128, false><<<aggBlocks, 256, 0, st>>>(
            p_hh, p_hs, p_hd, p_offs, p_csre, bb[0], b_c + 0,
            b_max + 0 + gph, p_xh, nullptr, N);
        gemm_mma_k<128><<<tcBlocks, 256, 71680, st>>>(
            p_xh, b_wbh, b_wbl, asrc[1], adst[1], p_hh, p_hs, p_hd,
            b_max + 2 + gph, N);
        gat_agg_k<128, false><<<aggBlocks, 256, 0, st>>>(
            p_hh, p_hs, p_hd, p_offs, p_csre, bb[1], b_c + 1,
            b_max + 2 + gph, p_xh, nullptr, N);
        gemm_mma_k<64><<<tcBlocks, 256, 55296, st>>>(
            p_xh, b_wbh + 128 * 128, b_wbl + 128 * 128, asrc[2], adst[2],
            p_hh, p_hs, p_hd, b_max + 4 + gph, N);
        gat_agg_k<64, true><<<aggBlocks, 256, 0, st>>>(
            p_hh, p_hs, p_hd, p_offs, p_csre, bb[2], b_c + 2,
            b_max + 4 + gph, nullptr, p_g + gph * 64, N);
    }

    cudaEventRecord(evJ, s1);
    cudaStreamWaitEvent((cudaStream_t)0, evJ, 0);
    head_k<<<1, 128, 0, 0>>>(p_g, xnorm[0], xnorm[1], Wlin, blin, Wc1, bc1, Wc2, bc2,
                             (float*)d_out, N);
}

// round 15
// speedup vs baseline: 1.1699x; 1.0352x over previous
#include <cuda_runtime.h>
#include <cuda_bf16.h>
#include <cuda_fp16.h>
#include <math.h>
#include <stdint.h>

// ---------------------------------------------------------------------------
// SpatialModel: 3-layer GATConv on two graphs (N=50000, E=800000), mean pool,
// MLP head -> [1,3] logits.
//
// R15: gemm_mma switched to fp16 MMA -- A = x (fp16, exact, no split),
// W split into fp16 hi+lo (2 passes instead of 3 bf16 passes; A smem
// conversion chain deleted). Otherwise R14: fp16 h/x payloads, x8+x4 agg,
// fused mean-pool on layer 2, two-stream pipeline, batched CSR side stream.
// ---------------------------------------------------------------------------

#define MAX_N 50000
#define MAX_E 800000
#define TILE 512

__device__ __align__(16) __half g_hh[2][MAX_N * 128];
__device__ __align__(16) __half g_xh[2][MAX_N * 128];
__device__ float g_hs[2][MAX_N];
__device__ float g_hd[2][MAX_N];
__device__ int   g_deg[2][MAX_N];
__device__ int   g_offs[2][MAX_N + 1];
__device__ int   g_cursor[2][MAX_N];
__device__ __align__(16) float2 g_csre[2][MAX_E];
__device__ int   g_tsum[2][128];
__device__ float g_c[3];
__device__ unsigned g_maxhs[6];
__device__ float g_gvec[128];
__device__ __align__(16) __half g_wfh[2][128 * 128];   // fp16 W hi
__device__ __align__(16) __half g_wfl[2][128 * 128];   // fp16 W lo

// ---------------------------------------------------------------------------
__device__ __forceinline__ uint32_t smem_u32(const void* p) {
    uint32_t a;
    asm("{ .reg .u64 t; cvta.to.shared.u64 t, %1; cvt.u32.u64 %0, t; }"
        : "=r"(a) : "l"(p));
    return a;
}
__device__ __forceinline__ unsigned fkey(float f) {
    int i = __float_as_int(f);
    return i >= 0 ? ((unsigned)i | 0x80000000u) : ~(unsigned)i;
}
__device__ __forceinline__ float funkey(unsigned k) {
    return (k & 0x80000000u) ? __int_as_float((int)(k & 0x7FFFFFFFu))
                             : __int_as_float((int)~k);
}
#define LDSM_X4(r0, r1, r2, r3, addr)                                          \
    asm volatile("ldmatrix.sync.aligned.m8n8.x4.shared.b16 {%0,%1,%2,%3}, [%4];" \
                 : "=r"(r0), "=r"(r1), "=r"(r2), "=r"(r3) : "r"(addr))
#define LDSM_X4_T(r0, r1, r2, r3, addr)                                        \
    asm volatile("ldmatrix.sync.aligned.m8n8.x4.trans.shared.b16 {%0,%1,%2,%3}, [%4];" \
                 : "=r"(r0), "=r"(r1), "=r"(r2), "=r"(r3) : "r"(addr))
__device__ __forceinline__ void mma_f16(float* c, uint32_t a0, uint32_t a1,
                                        uint32_t a2, uint32_t a3,
                                        uint32_t b0, uint32_t b1) {
    asm volatile(
        "mma.sync.aligned.m16n8k16.row.col.f32.f16.f16.f32 "
        "{%0,%1,%2,%3}, {%4,%5,%6,%7}, {%8,%9}, {%0,%1,%2,%3};"
        : "+f"(c[0]), "+f"(c[1]), "+f"(c[2]), "+f"(c[3])
        : "r"(a0), "r"(a1), "r"(a2), "r"(a3), "r"(b0), "r"(b1));
}

// ---------------------------------------------------------------------------
__global__ void build_deg_k(const int* __restrict__ ei0, const int* __restrict__ ei1,
                            int* deg, int E) {
    int i = (blockIdx.x * blockDim.x + threadIdx.x) * 2;
    if (i >= 2 * E) return;
    int g = (i >= E);
    int j = i - g * E;
    const int* dst = (g ? ei1 : ei0) + E;
    int d0 = dst[j];
    int d1 = dst[j + 1];
    atomicAdd(&deg[g * MAX_N + d0], 1);
    atomicAdd(&deg[g * MAX_N + d1], 1);
}

__global__ void scan1_k(const int* __restrict__ deg, int* tsum, int n, int nT) {
    __shared__ int sh[256];
    int bx = blockIdx.x, t = threadIdx.x;
    int g = (bx >= nT);
    int b = bx - g * nT;
    const int* dg = deg + g * MAX_N;
    int i0 = b * TILE;
    int s = 0;
    int i = i0 + t;        if (i < n) s += dg[i];
    i = i0 + 256 + t;      if (i < n) s += dg[i];
    sh[t] = s;
    __syncthreads();
    for (int o = 128; o; o >>= 1) { if (t < o) sh[t] += sh[t + o]; __syncthreads(); }
    if (t == 0) tsum[g * 128 + b] = sh[0];
}
__global__ void scan2_k(int* tsum, int nT) {
    __shared__ int sh[256];
    int t = threadIdx.x;
    int g = t >> 7, tl = t & 127;
    int v0 = (tl < nT) ? tsum[g * 128 + tl] : 0;
    sh[t] = v0;
    __syncthreads();
    for (int d = 1; d < 128; d <<= 1) {
        int v = (tl >= d) ? sh[t - d] : 0;
        __syncthreads();
        sh[t] += v;
        __syncthreads();
    }
    if (tl < nT) tsum[g * 128 + tl] = sh[t] - v0;
}
__global__ void scan3_k(const int* __restrict__ deg, const int* __restrict__ tsum,
                        int* offs, int* cursor, int n, int nT) {
    __shared__ int sh[TILE];
    int bx = blockIdx.x, t = threadIdx.x;
    int g = (bx >= nT);
    int b = bx - g * nT;
    const int* dg = deg + g * MAX_N;
    const int* ts = tsum + g * 128;
    int* of = offs + g * (MAX_N + 1);
    int* cu = cursor + g * MAX_N;
    int i = b * TILE + t;
    int d = (i < n) ? dg[i] : 0;
    sh[t] = d;
    __syncthreads();
    for (int o = 1; o < TILE; o <<= 1) {
        int v = (t >= o) ? sh[t - o] : 0;
        __syncthreads();
        sh[t] += v;
        __syncthreads();
    }
    if (i < n) {
        int base = ts[b];
        int off = base + sh[t] - d;
        of[i] = off;
        cu[i] = off;
        if (i == n - 1) of[n] = base + sh[t];
    }
}

__global__ void scatter_k(const int* __restrict__ ei0, const float* __restrict__ col0,
                          const int* __restrict__ ei1, const float* __restrict__ col1,
                          int* cursor, float2* csre, int E) {
    int i = (blockIdx.x * blockDim.x + threadIdx.x) * 2;
    if (i >= 2 * E) return;
    int g = (i >= E);
    int j = i - g * E;
    const int* ei = g ? ei1 : ei0;
    const float* col = g ? col1 : col0;
    int* cur = cursor + g * MAX_N;
    float2* cs = csre + (size_t)g * MAX_E;
    int s0 = ei[j], s1 = ei[j + 1];
    int d0 = ei[E + j], d1 = ei[E + j + 1];
    float c0 = col[j], c1 = col[j + 1];
    int p0 = atomicAdd(&cur[d0], 1);
    int p1 = atomicAdd(&cur[d1], 1);
    cs[p0] = make_float2(__int_as_float(s0), c0);
    cs[p1] = make_float2(__int_as_float(s1), c1);
}

// ---------------------------------------------------------------------------
// split fp32 W -> fp16 hi + fp16 lo (|W - Wh - Wl| <= 2^-22 |W|)
__global__ void wsplit_k(const float* __restrict__ W, __half* hi, __half* lo, int n) {
    int i = blockIdx.x * blockDim.x + threadIdx.x;
    if (i >= n) return;
    float v = W[i];
    __half h = __float2half_rn(v);
    hi[i] = h;
    lo[i] = __float2half_rn(v - __half2float(h));
}

__global__ void cscalar3_k(const float* __restrict__ We1, const float* __restrict__ ae1,
                           const float* __restrict__ We2, const float* __restrict__ ae2,
                           const float* __restrict__ We3, const float* __restrict__ ae3,
                           float* out) {
    int w = threadIdx.x >> 5, lane = threadIdx.x & 31;
    if (w >= 3) return;
    const float* We = (w == 0) ? We1 : (w == 1) ? We2 : We3;
    const float* ae = (w == 0) ? ae1 : (w == 1) ? ae2 : ae3;
    int C = (w == 2) ? 64 : 128;
    float s = 0.f;
    for (int k = lane; k < C; k += 32) s += We[k] * ae[k];
    #pragma unroll
    for (int o = 16; o; o >>= 1) s += __shfl_xor_sync(0xffffffffu, s, o);
    if (lane == 0) out[w] = s;
}

// ---------------------------------------------------------------------------
__global__ void __launch_bounds__(256)
gemm7_k(const float* __restrict__ x, const float* __restrict__ W,
        const float* __restrict__ asrc, const float* __restrict__ adst,
        __half* __restrict__ h, float* __restrict__ hs, float* __restrict__ hd,
        unsigned* __restrict__ gmax, int M) {
    __shared__ float Ws[7 * 128], As[128], Ad[128];
    __shared__ float wmax[8];
    int t = threadIdx.x;
    for (int i = t; i < 7 * 128; i += 256) Ws[i] = W[i];
    if (t < 128) { As[t] = asrc[t]; Ad[t] = adst[t]; }
    __syncthreads();
    int r = blockIdx.x * 8 + (t >> 5);
    bool active = (r < M);
    int lane = t & 31, c0 = lane * 4;
    float s = 0.f, d = 0.f;
    if (active) {
        float xv[7];
        #pragma unroll
        for (int k = 0; k < 7; k++) xv[k] = x[(size_t)r * 7 + k];
        float out[4];
        #pragma unroll
        for (int j = 0; j < 4; j++) {
            float acc = 0.f;
            #pragma unroll
            for (int k = 0; k < 7; k++) acc += xv[k] * Ws[k * 128 + c0 + j];
            out[j] = acc;
        }
        __half2 p0 = __floats2half2_rn(out[0], out[1]);
        __half2 p1 = __floats2half2_rn(out[2], out[3]);
        uint2 u = make_uint2(*(uint32_t*)&p0, *(uint32_t*)&p1);
        *(uint2*)(h + (size_t)r * 128 + c0) = u;
        s = out[0] * As[c0] + out[1] * As[c0 + 1] + out[2] * As[c0 + 2] + out[3] * As[c0 + 3];
        d = out[0] * Ad[c0] + out[1] * Ad[c0 + 1] + out[2] * Ad[c0 + 2] + out[3] * Ad[c0 + 3];
        #pragma unroll
        for (int o = 16; o; o >>= 1) {
            s += __shfl_xor_sync(0xffffffffu, s, o);
            d += __shfl_xor_sync(0xffffffffu, d, o);
        }
        if (lane == 0) { hs[r] = s; hd[r] = d; }
    }
    if (lane == 0) wmax[t >> 5] = active ? s : -3.4e38f;
    __syncthreads();
    if (t == 0) {
        float m = wmax[0];
        #pragma unroll
        for (int i = 1; i < 8; i++) m = fmaxf(m, wmax[i]);
        atomicMax(gmax, fkey(m));
    }
}

// ---------------------------------------------------------------------------
// fp16 MMA GEMM: H = A(fp16, exact) @ (Wh + Wl), 2 passes. Fused dots + max.
template <int CN>
__global__ void __launch_bounds__(256, 2)
gemm_mma_k(const __half* __restrict__ A, const __half* __restrict__ Bh,
           const __half* __restrict__ Bl,
           const float* __restrict__ asrc, const float* __restrict__ adst,
           __half* __restrict__ H, float* __restrict__ hs, float* __restrict__ hd,
           unsigned* __restrict__ gmax, int M) {
    extern __shared__ char smem[];
    constexpr int SA = 72;
    constexpr int SB = CN + 8;
    constexpr int AS = 0;
    constexpr int BH = 128 * SA * 2;                // 18432
    constexpr int BL = BH + 64 * SB * 2;
    constexpr int NT = CN / 16;
    constexpr int NC8 = CN / 8;

    int tid = threadIdx.x, lane = tid & 31, warp = tid >> 5;
    const int rowBase = blockIdx.x * 128;

    __half* as = (__half*)(smem + AS);
    __half* bs_h = (__half*)(smem + BH);
    __half* bs_l = (__half*)(smem + BL);

    int wm = warp >> 1, wn = warp & 1;
    int m0 = wm * 32, n0 = wn * (CN / 2);

    float acc[2][NT][4];
    #pragma unroll
    for (int a = 0; a < 2; a++)
        #pragma unroll
        for (int b = 0; b < NT; b++)
            #pragma unroll
            for (int q = 0; q < 4; q++) acc[a][b][q] = 0.f;

    int lr = lane & 15, lc = lane >> 4;
    uint32_t sb_a = smem_u32(as);
    uint32_t sb_bh = smem_u32(bs_h), sb_bl = smem_u32(bs_l);

    #pragma unroll
    for (int kc = 0; kc < 128; kc += 64) {
        // copy A chunk (128 rows x 64 halfs), pure uint4 copy
        #pragma unroll
        for (int q = 0; q < 4; q++) {
            int i = q * 256 + tid;
            int r = i >> 3, c8 = i & 7;
            int gr = rowBase + r;
            uint4 u = make_uint4(0u, 0u, 0u, 0u);
            if (gr < M) u = *(const uint4*)(A + (size_t)gr * 128 + kc + c8 * 8);
            *(uint4*)(as + r * SA + c8 * 8) = u;
        }
        for (int i = tid; i < 64 * NC8; i += 256) {
            int r = i / NC8, c8 = i % NC8;
            int gi = (kc + r) * NC8 + c8;
            *(uint4*)(bs_h + r * SB + c8 * 8) = ((const uint4*)Bh)[gi];
            *(uint4*)(bs_l + r * SB + c8 * 8) = ((const uint4*)Bl)[gi];
        }
        __syncthreads();

        #pragma unroll
        for (int ks = 0; ks < 4; ks++) {
            int k0 = ks * 16;
            uint32_t af[2][4];
            #pragma unroll
            for (int mt = 0; mt < 2; mt++) {
                uint32_t off = ((m0 + mt * 16 + lr) * SA + k0 + lc * 8) * 2;
                LDSM_X4(af[mt][0], af[mt][1], af[mt][2], af[mt][3], sb_a + off);
            }
            #pragma unroll
            for (int n16 = 0; n16 < NT / 2; n16++) {
                uint32_t off = ((k0 + lr) * SB + n0 + n16 * 16 + lc * 8) * 2;
                uint32_t b0h, b1h, b2h, b3h, b0l, b1l, b2l, b3l;
                LDSM_X4_T(b0h, b1h, b2h, b3h, sb_bh + off);
                LDSM_X4_T(b0l, b1l, b2l, b3l, sb_bl + off);
                int nt0 = 2 * n16, nt1 = 2 * n16 + 1;
                #pragma unroll
                for (int mt = 0; mt < 2; mt++) {
                    mma_f16(acc[mt][nt0], af[mt][0], af[mt][1], af[mt][2], af[mt][3], b0h, b1h);
                    mma_f16(acc[mt][nt0], af[mt][0], af[mt][1], af[mt][2], af[mt][3], b0l, b1l);
                    mma_f16(acc[mt][nt1], af[mt][0], af[mt][1], af[mt][2], af[mt][3], b2h, b3h);
                    mma_f16(acc[mt][nt1], af[mt][0], af[mt][1], af[mt][2], af[mt][3], b2l, b3l);
                }
            }
        }
        __syncthreads();
    }

    int g = lane >> 2, tig = lane & 3;
    #pragma unroll
    for (int mt = 0; mt < 2; mt++) {
        int r0 = rowBase + m0 + mt * 16 + g;
        int r1 = r0 + 8;
        #pragma unroll
        for (int nt = 0; nt < NT; nt++) {
            int col = n0 + nt * 8 + tig * 2;
            if (r0 < M)
                *(__half2*)(H + (size_t)r0 * CN + col) =
                    __floats2half2_rn(acc[mt][nt][0], acc[mt][nt][1]);
            if (r1 < M)
                *(__half2*)(H + (size_t)r1 * CN + col) =
                    __floats2half2_rn(acc[mt][nt][2], acc[mt][nt][3]);
        }
    }

    float sd[2][2] = {}, dd[2][2] = {};
    #pragma unroll
    for (int mt = 0; mt < 2; mt++)
        #pragma unroll
        for (int nt = 0; nt < NT; nt++) {
            int col = n0 + nt * 8 + tig * 2;
            float a0 = __ldg(asrc + col), a1 = __ldg(asrc + col + 1);
            float d0 = __ldg(adst + col), d1 = __ldg(adst + col + 1);
            sd[mt][0] += acc[mt][nt][0] * a0 + acc[mt][nt][1] * a1;
            dd[mt][0] += acc[mt][nt][0] * d0 + acc[mt][nt][1] * d1;
            sd[mt][1] += acc[mt][nt][2] * a0 + acc[mt][nt][3] * a1;
            dd[mt][1] += acc[mt][nt][2] * d0 + acc[mt][nt][3] * d1;
        }
    #pragma unroll
    for (int o = 1; o < 4; o <<= 1) {
        #pragma unroll
        for (int mt = 0; mt < 2; mt++)
            #pragma unroll
            for (int j = 0; j < 2; j++) {
                sd[mt][j] += __shfl_xor_sync(0xffffffffu, sd[mt][j], o);
                dd[mt][j] += __shfl_xor_sync(0xffffffffu, dd[mt][j], o);
            }
    }
    __syncthreads();
    float* red = (float*)smem;
    if (wn == 1 && tig == 0) {
        #pragma unroll
        for (int mt = 0; mt < 2; mt++)
            #pragma unroll
            for (int j = 0; j < 2; j++) {
                int lrow = m0 + mt * 16 + g + j * 8;
                red[lrow] = sd[mt][j];
                red[128 + lrow] = dd[mt][j];
            }
    }
    __syncthreads();
    float hsmax = -3.4e38f;
    if (wn == 0 && tig == 0) {
        #pragma unroll
        for (int mt = 0; mt < 2; mt++)
            #pragma unroll
            for (int j = 0; j < 2; j++) {
                int lrow = m0 + mt * 16 + g + j * 8;
                int gr = rowBase + lrow;
                if (gr < M) {
                    float sv = sd[mt][j] + red[lrow];
                    hs[gr] = sv;
                    hd[gr] = dd[mt][j] + red[128 + lrow];
                    hsmax = fmaxf(hsmax, sv);
                }
            }
    }
    #pragma unroll
    for (int o = 16; o; o >>= 1)
        hsmax = fmaxf(hsmax, __shfl_xor_sync(0xffffffffu, hsmax, o));
    if (wn == 0 && lane == 0) atomicMax(gmax, fkey(hsmax));
}

// ---------------------------------------------------------------------------
__device__ __forceinline__ float leaky02(float a) {
    return a > 0.f ? a : 0.2f * a;
}

template <int C, bool POOL>
__global__ void __launch_bounds__(256)
gat_agg_k(const __half* __restrict__ h, const float* __restrict__ hs,
          const float* __restrict__ hd, const int* __restrict__ offs,
          const float2* __restrict__ csre,
          const float* __restrict__ bias,
          const float* __restrict__ cptr, const unsigned* __restrict__ gmax,
          __half* __restrict__ xout, float* __restrict__ gsum, int n) {
    constexpr int VL = C / 32;
    __shared__ float sums[64];
    int w = (blockIdx.x * blockDim.x + threadIdx.x) >> 5;
    int lane = threadIdx.x & 31;
    bool active = (w < n);

    if (POOL) {
        if (threadIdx.x < 64) sums[threadIdx.x] = 0.f;
        __syncthreads();
    }

    float out[VL];
    if (active) {
        float c = *cptr;
        float hdn = hd[w];
        float ub = leaky02(funkey(*gmax) + hdn + fmaxf(c, 0.f));
        int beg = offs[w], end = offs[w + 1];

        float acc[VL];
        #pragma unroll
        for (int j = 0; j < VL; j++) acc[j] = 0.f;
        float denom = 0.f;
        float colsum = 0.f;
        const size_t loff = (size_t)lane * VL;

        int e = beg;
        for (; e + 8 <= end; e += 8) {
            float2 p[8]; int s[8]; float ex[8];
            #pragma unroll
            for (int q = 0; q < 8; q++) p[q] = csre[e + q];
            #pragma unroll
            for (int q = 0; q < 8; q++) {
                s[q] = __float_as_int(p[q].x);
                colsum += p[q].y;
            }
            #pragma unroll
            for (int q = 0; q < 8; q++) {
                ex[q] = __expf(leaky02(hs[s[q]] + hdn + p[q].y * c) - ub);
                denom += ex[q];
            }
            if (VL == 4) {
                uint2 r[8];
                #pragma unroll
                for (int q = 0; q < 8; q++)
                    r[q] = *(const uint2*)(h + (size_t)s[q] * C + loff);
                #pragma unroll
                for (int q = 0; q < 8; q++) {
                    float2 a = __half22float2(*(__half2*)&r[q].x);
                    float2 b = __half22float2(*(__half2*)&r[q].y);
                    acc[0] += ex[q] * a.x; acc[1] += ex[q] * a.y;
                    acc[2] += ex[q] * b.x; acc[3] += ex[q] * b.y;
                }
            } else {
                uint32_t r[8];
                #pragma unroll
                for (int q = 0; q < 8; q++)
                    r[q] = *(const uint32_t*)(h + (size_t)s[q] * C + loff);
                #pragma unroll
                for (int q = 0; q < 8; q++) {
                    float2 a = __half22float2(*(__half2*)&r[q]);
                    acc[0] += ex[q] * a.x; acc[1] += ex[q] * a.y;
                }
            }
        }
        for (; e + 4 <= end; e += 4) {
            float2 p[4]; int s[4]; float ex[4];
            #pragma unroll
            for (int q = 0; q < 4; q++) p[q] = csre[e + q];
            #pragma unroll
            for (int q = 0; q < 4; q++) {
                s[q] = __float_as_int(p[q].x);
                colsum += p[q].y;
            }
            #pragma unroll
            for (int q = 0; q < 4; q++) {
                ex[q] = __expf(leaky02(hs[s[q]] + hdn + p[q].y * c) - ub);
                denom += ex[q];
            }
            if (VL == 4) {
                uint2 r[4];
                #pragma unroll
                for (int q = 0; q < 4; q++)
                    r[q] = *(const uint2*)(h + (size_t)s[q] * C + loff);
                #pragma unroll
                for (int q = 0; q < 4; q++) {
                    float2 a = __half22float2(*(__half2*)&r[q].x);
                    float2 b = __half22float2(*(__half2*)&r[q].y);
                    acc[0] += ex[q] * a.x; acc[1] += ex[q] * a.y;
                    acc[2] += ex[q] * b.x; acc[3] += ex[q] * b.y;
                }
            } else {
                uint32_t r[4];
                #pragma unroll
                for (int q = 0; q < 4; q++)
                    r[q] = *(const uint32_t*)(h + (size_t)s[q] * C + loff);
                #pragma unroll
                for (int q = 0; q < 4; q++) {
                    float2 a = __half22float2(*(__half2*)&r[q]);
                    acc[0] += ex[q] * a.x; acc[1] += ex[q] * a.y;
                }
            }
        }
        for (; e < end; e++) {
            float2 p = csre[e];
            int s = __float_as_int(p.x);
            colsum += p.y;
            float ex = __expf(leaky02(hs[s] + hdn + p.y * c) - ub);
            denom += ex;
            if (VL == 4) {
                uint2 r = *(const uint2*)(h + (size_t)s * C + loff);
                float2 a = __half22float2(*(__half2*)&r.x);
                float2 b = __half22float2(*(__half2*)&r.y);
                acc[0] += ex * a.x; acc[1] += ex * a.y;
                acc[2] += ex * b.x; acc[3] += ex * b.y;
            } else {
                uint32_t r = *(const uint32_t*)(h + (size_t)s * C + loff);
                float2 a = __half22float2(*(__half2*)&r);
                acc[0] += ex * a.x; acc[1] += ex * a.y;
            }
        }
        {   // self loop
            int deg = end - beg;
            float lattr = colsum / (float)(deg > 1 ? deg : 1);
            float aself = leaky02(hs[w] + hdn + lattr * c);
            float ex = __expf(aself - ub);
            denom += ex;
            if (VL == 4) {
                uint2 r = *(const uint2*)(h + (size_t)w * C + loff);
                float2 a = __half22float2(*(__half2*)&r.x);
                float2 b = __half22float2(*(__half2*)&r.y);
                acc[0] += ex * a.x; acc[1] += ex * a.y;
                acc[2] += ex * b.x; acc[3] += ex * b.y;
            } else {
                uint32_t r = *(const uint32_t*)(h + (size_t)w * C + loff);
                float2 a = __half22float2(*(__half2*)&r);
                acc[0] += ex * a.x; acc[1] += ex * a.y;
            }
        }
        float inv = 1.f / denom;
        #pragma unroll
        for (int j = 0; j < VL; j++) {
            float v = acc[j] * inv + bias[loff + j];
            out[j] = v > 0.f ? v : expm1f(v);
        }
        if (!POOL) {
            __half* xr = xout + (size_t)w * C + loff;
            if (VL == 4) {
                __half2 q0 = __floats2half2_rn(out[0], out[1]);
                __half2 q1 = __floats2half2_rn(out[2], out[3]);
                *(uint2*)xr = make_uint2(*(uint32_t*)&q0, *(uint32_t*)&q1);
            } else {
                __half2 q0 = __floats2half2_rn(out[0], out[1]);
                *(uint32_t*)xr = *(uint32_t*)&q0;
            }
        }
    }
    if (POOL) {
        if (active) {
            #pragma unroll
            for (int j = 0; j < VL; j++)
                atomicAdd(&sums[lane * VL + j], out[j]);
        }
        __syncthreads();
        if (threadIdx.x < 64) atomicAdd(&gsum[threadIdx.x], sums[threadIdx.x]);
    }
}

__global__ void head_k(const float* __restrict__ g, const float* __restrict__ xn1,
                       const float* __restrict__ xn2, const float* __restrict__ Wlin,
                       const float* __restrict__ blin, const float* __restrict__ Wc1,
                       const float* __restrict__ bc1, const float* __restrict__ Wc2,
                       const float* __restrict__ bc2, float* __restrict__ out, int n) {
    __shared__ float v[128];
    __shared__ float hh[16];
    int t = threadIdx.x;
    int gi = t >> 6, c = t & 63;
    const float* gg = g + gi * 64;
    const float* xn = gi ? xn2 : xn1;
    float inv = 1.f / (float)n;
    float s = blin[c];
    for (int k = 0; k < 64; k++) s += (gg[k] * inv) * Wlin[k * 64 + c];
    for (int k = 0; k < 16; k++) s += xn[k] * Wlin[(64 + k) * 64 + c];
    v[t] = s;
    __syncthreads();
    if (t < 16) {
        float a = bc1[t];
        for (int k = 0; k < 128; k++) a += v[k] * Wc1[k * 16 + t];
        hh[t] = fmaxf(a, 0.f);
    }
    __syncthreads();
    if (t < 3) {
        float a = bc2[t];
        for (int k = 0; k < 16; k++) a += hh[k] * Wc2[k * 3 + t];
        out[t] = a;
    }
}

// ---------------------------------------------------------------------------
extern "C" void kernel_launch(void* const* d_in, const int* in_sizes, int n_in,
                              void* d_out, int out_size) {
    const int IN = 7;
    const int N = in_sizes[0] / IN;
    const int E = in_sizes[2] / 2;

    static cudaStream_t s1 = nullptr, sCsr = nullptr;
    static cudaEvent_t evF = nullptr, evP = nullptr, evC = nullptr, evJ = nullptr;
    if (!s1) {
        cudaStreamCreateWithFlags(&s1, cudaStreamNonBlocking);
        cudaStreamCreateWithFlags(&sCsr, cudaStreamNonBlocking);
        cudaEventCreateWithFlags(&evF, cudaEventDisableTiming);
        cudaEventCreateWithFlags(&evP, cudaEventDisableTiming);
        cudaEventCreateWithFlags(&evC, cudaEventDisableTiming);
        cudaEventCreateWithFlags(&evJ, cudaEventDisableTiming);
        cudaFuncSetAttribute(gemm_mma_k<128>,
                             cudaFuncAttributeMaxDynamicSharedMemorySize, 53248);
        cudaFuncSetAttribute(gemm_mma_k<64>,
                             cudaFuncAttributeMaxDynamicSharedMemorySize, 36864);
    }

    float *b_hs, *b_hd, *p_g, *b_c;
    float2* b_csre;
    __half *b_hh, *b_xh, *b_wfh, *b_wfl;
    unsigned* b_max;
    int *b_deg, *b_offs, *b_cursor, *b_tsum;
    cudaGetSymbolAddress((void**)&b_hh, g_hh);
    cudaGetSymbolAddress((void**)&b_xh, g_xh);
    cudaGetSymbolAddress((void**)&b_hs, g_hs);
    cudaGetSymbolAddress((void**)&b_hd, g_hd);
    cudaGetSymbolAddress((void**)&b_csre, g_csre);
    cudaGetSymbolAddress((void**)&p_g, g_gvec);
    cudaGetSymbolAddress((void**)&b_c, g_c);
    cudaGetSymbolAddress((void**)&b_max, g_maxhs);
    cudaGetSymbolAddress((void**)&b_deg, g_deg);
    cudaGetSymbolAddress((void**)&b_offs, g_offs);
    cudaGetSymbolAddress((void**)&b_cursor, g_cursor);
    cudaGetSymbolAddress((void**)&b_tsum, g_tsum);
    cudaGetSymbolAddress((void**)&b_wfh, g_wfh);
    cudaGetSymbolAddress((void**)&b_wfl, g_wfl);

    const float* x_in[2]  = {(const float*)d_in[0], (const float*)d_in[1]};
    const int*   ei[2]    = {(const int*)d_in[2], (const int*)d_in[3]};
    const float* xnorm[2] = {(const float*)d_in[4], (const float*)d_in[5]};
    const float* ecol[2]  = {(const float*)d_in[6], (const float*)d_in[7]};

    const float* W[3]; const float* asrc[3]; const float* adst[3];
    const float* We[3]; const float* ae[3]; const float* bb[3];
    for (int l = 0; l < 3; l++) {
        W[l]    = (const float*)d_in[8 + 6 * l + 0];
        asrc[l] = (const float*)d_in[8 + 6 * l + 1];
        adst[l] = (const float*)d_in[8 + 6 * l + 2];
        We[l]   = (const float*)d_in[8 + 6 * l + 3];
        ae[l]   = (const float*)d_in[8 + 6 * l + 4];
        bb[l]   = (const float*)d_in[8 + 6 * l + 5];
    }
    const float* Wlin = (const float*)d_in[26];
    const float* blin = (const float*)d_in[27];
    const float* Wc1  = (const float*)d_in[28];
    const float* bc1  = (const float*)d_in[29];
    const float* Wc2  = (const float*)d_in[30];
    const float* bc2  = (const float*)d_in[31];

    const int eHalfBlocks = (E + 255) / 256;
    const int nT = (N + TILE - 1) / TILE;
    const int tcBlocks = (N + 127) / 128;
    const int g7Blocks = (N + 7) / 8;
    const int aggBlocks = (N * 32 + 255) / 256;

    // fork point
    cudaEventRecord(evF, 0);
    cudaStreamWaitEvent(sCsr, evF, 0);
    cudaStreamWaitEvent(s1, evF, 0);

    // batched CSR build on side stream
    cudaMemsetAsync(b_deg, 0, 2 * MAX_N * sizeof(int), sCsr);
    build_deg_k<<<eHalfBlocks, 256, 0, sCsr>>>(ei[0], ei[1], b_deg, E);
    scan1_k<<<2 * nT, 256, 0, sCsr>>>(b_deg, b_tsum, N, nT);
    scan2_k<<<1, 256, 0, sCsr>>>(b_tsum, nT);
    scan3_k<<<2 * nT, TILE, 0, sCsr>>>(b_deg, b_tsum, b_offs, b_cursor, N, nT);
    scatter_k<<<eHalfBlocks, 256, 0, sCsr>>>(ei[0], ecol[0], ei[1], ecol[1],
                                             b_cursor, b_csre, E);
    cudaEventRecord(evC, sCsr);

    // prologue on stream 0 (graph-invariant)
    cudaMemsetAsync(p_g, 0, 128 * sizeof(float), 0);
    cudaMemsetAsync(b_max, 0, 6 * sizeof(unsigned), 0);
    wsplit_k<<<(128 * 128 + 255) / 256, 256, 0, 0>>>(W[1], b_wfh, b_wfl, 128 * 128);
    wsplit_k<<<(128 * 64 + 255) / 256, 256, 0, 0>>>(W[2], b_wfh + 128 * 128,
                                                    b_wfl + 128 * 128, 128 * 64);
    cscalar3_k<<<1, 96, 0, 0>>>(We[0], ae[0], We[1], ae[1], We[2], ae[2], b_c);
    cudaEventRecord(evP, 0);
    cudaStreamWaitEvent(s1, evP, 0);

    // per-graph chains on two streams
    for (int gph = 0; gph < 2; gph++) {
        cudaStream_t st = gph ? s1 : (cudaStream_t)0;
        __half* p_hh = b_hh + (size_t)gph * MAX_N * 128;
        __half* p_xh = b_xh + (size_t)gph * MAX_N * 128;
        float* p_hs = b_hs + gph * MAX_N;
        float* p_hd = b_hd + gph * MAX_N;
        float2* p_csre = b_csre + (size_t)gph * MAX_E;
        int* p_offs = b_offs + gph * (MAX_N + 1);

        gemm7_k<<<g7Blocks, 256, 0, st>>>(x_in[gph], W[0], asrc[0], adst[0],
                                          p_hh, p_hs, p_hd, b_max + 0 + gph, N);
        cudaStreamWaitEvent(st, evC, 0);

        gat_agg_k<128, false><<<aggBlocks, 256, 0, st>>>(
            p_hh, p_hs, p_hd, p_offs, p_csre, bb[0], b_c + 0,
            b_max + 0 + gph, p_xh, nullptr, N);
        gemm_mma_k<128><<<tcBlocks, 256, 53248, st>>>(
            p_xh, b_wfh, b_wfl, asrc[1], adst[1], p_hh, p_hs, p_hd,
            b_max + 2 + gph, N);
        gat_agg_k<128, false><<<aggBlocks, 256, 0, st>>>(
            p_hh, p_hs, p_hd, p_offs, p_csre, bb[1], b_c + 1,
            b_max + 2 + gph, p_xh, nullptr, N);
        gemm_mma_k<64><<<tcBlocks, 256, 36864, st>>>(
            p_xh, b_wfh + 128 * 128, b_wfl + 128 * 128, asrc[2], adst[2],
            p_hh, p_hs, p_hd, b_max + 4 + gph, N);
        gat_agg_k<64, true><<<aggBlocks, 256, 0, st>>>(
            p_hh, p_hs, p_hd, p_offs, p_csre, bb[2], b_c + 2,
            b_max + 4 + gph, nullptr, p_g + gph * 64, N);
    }

    cudaEventRecord(evJ, s1);
    cudaStreamWaitEvent((cudaStream_t)0, evJ, 0);
    head_k<<<1, 128, 0, 0>>>(p_g, xnorm[0], xnorm[1], Wlin, blin, Wc1, bc1, Wc2, bc2,
                             (float*)d_out, N);
}